// round 4
// baseline (speedup 1.0000x reference)
#include <cuda_runtime.h>
#include <cuda_bf16.h>
#include <stdint.h>

#define NNODES 50000
#define NEDGES 800000
#define MTILE 64
#define NTILES (NEDGES / MTILE)   // 12500
#define EDGE_GRID 296

// ---------------- scratch ----------------
__device__ __align__(128) __nv_bfloat16 g_hAB[(size_t)NNODES * 256];
__device__ __align__(128) __nv_bfloat16 g_W1T[2 * 128 * 128];
__device__ float g_sA[NNODES];
__device__ float g_sB[NNODES];
__device__ float g_agg[NNODES * 9];

// ---------------- helpers ----------------
static __device__ __forceinline__ uint32_t packbf(float a, float b) {
    __nv_bfloat162 h = __floats2bfloat162_rn(a, b);
    return *reinterpret_cast<uint32_t*>(&h);
}
static __device__ __forceinline__ float2 unpackbf(uint32_t u) {
    __nv_bfloat162 h; *reinterpret_cast<uint32_t*>(&h) = u;
    return __bfloat1622float2(h);
}
static __device__ __forceinline__ void mma16816(float* c, const uint32_t* a, const uint32_t* b) {
    asm volatile(
        "mma.sync.aligned.m16n8k16.row.col.f32.bf16.bf16.f32 "
        "{%0,%1,%2,%3}, {%4,%5,%6,%7}, {%8,%9}, {%0,%1,%2,%3};\n"
        : "+f"(c[0]), "+f"(c[1]), "+f"(c[2]), "+f"(c[3])
        : "r"(a[0]), "r"(a[1]), "r"(a[2]), "r"(a[3]), "r"(b[0]), "r"(b[1]));
}
static __device__ __forceinline__ void ldsm4(uint32_t* r, uint32_t addr) {
    asm volatile("ldmatrix.sync.aligned.m8n8.x4.shared.b16 {%0,%1,%2,%3}, [%4];"
        : "=r"(r[0]), "=r"(r[1]), "=r"(r[2]), "=r"(r[3]) : "r"(addr));
}
static __device__ __forceinline__ float silu_f(float x) {
    return __fdividef(x, 1.0f + __expf(-x));
}
static __device__ __forceinline__ uint32_t s2u(const void* p) {
    return (uint32_t)__cvta_generic_to_shared(p);
}
static __device__ __forceinline__ void cpa16(uint32_t dst, const void* src) {
    asm volatile("cp.async.cg.shared.global [%0], [%1], 16;" :: "r"(dst), "l"(src));
}

// ---------------------------------------------------------------------------
// prep: W1 -> bf16 transposed halves; zero agg
// ---------------------------------------------------------------------------
__global__ void prep_kernel(const float* __restrict__ W1) {
    int i = blockIdx.x * 256 + threadIdx.x;
    if (i < 2 * 128 * 128) {
        int hb = i >> 14, n = (i >> 7) & 127, k = i & 127;
        g_W1T[i] = __float2bfloat16(W1[(size_t)(hb * 128 + k) * 128 + n]);
    }
    if (i < NNODES * 9) g_agg[i] = 0.f;
}

// ---------------------------------------------------------------------------
// hab: hA' = h @ W1[0:128] + b1 ; hB = h @ W1[128:256]; row sums to g_sA/g_sB
// ---------------------------------------------------------------------------
#define HAB_SMEM (17408 + 34816 + 1024)
__global__ void __launch_bounds__(256, 2)
hab_kernel(const float* __restrict__ h, const float* __restrict__ b1) {
    extern __shared__ unsigned char sm[];
    unsigned char* smA = sm;             // 64 x 272B
    unsigned char* smB = sm + 17408;     // 128 x 272B
    float* part = (float*)(sm + 52224);  // 64 x 4 floats

    const int tid = threadIdx.x;
    const int nt0 = blockIdx.x * 64;
    const int hb = blockIdx.y;

    for (int idx = tid; idx < 64 * 32; idx += 256) {
        int i = idx >> 5, kq = idx & 31;
        float4 v = make_float4(0.f, 0.f, 0.f, 0.f);
        if (nt0 + i < NNODES) v = *(const float4*)(h + (size_t)(nt0 + i) * 128 + kq * 4);
        *(uint2*)(smA + i * 272 + kq * 8) = make_uint2(packbf(v.x, v.y), packbf(v.z, v.w));
    }
    const uint4* w1src = (const uint4*)(g_W1T + (hb << 14));
    for (int idx = tid; idx < 128 * 16; idx += 256) {
        int n = idx >> 4, q = idx & 15;
        *(uint4*)(smB + n * 272 + q * 16) = w1src[idx];
    }
    __syncthreads();

    const int warp = tid >> 5, lane = tid & 31;
    const int lr = lane & 7, sel = lane >> 3, g = lane >> 2, t = lane & 3;
    const int R0 = (warp & 1) * 32, wc = warp >> 1, C0 = wc * 32;

    uint32_t aAddr[2], bAddr[2];
#pragma unroll
    for (int mt = 0; mt < 2; mt++)
        aAddr[mt] = s2u(smA + (R0 + 16 * mt + lr + (sel & 1) * 8) * 272 + (sel >> 1) * 16);
#pragma unroll
    for (int np = 0; np < 2; np++)
        bAddr[np] = s2u(smB + (C0 + 16 * np + lr + (sel >> 1) * 8) * 272 + (sel & 1) * 16);

    float acc[2][4][4];
#pragma unroll
    for (int mt = 0; mt < 2; mt++)
#pragma unroll
        for (int nt = 0; nt < 4; nt++)
#pragma unroll
            for (int u = 0; u < 4; u++) acc[mt][nt][u] = 0.f;

#pragma unroll
    for (int kb = 0; kb < 8; kb++) {
        uint32_t a[2][4], b[2][4];
        ldsm4(a[0], aAddr[0] + kb * 32);
        ldsm4(a[1], aAddr[1] + kb * 32);
        ldsm4(b[0], bAddr[0] + kb * 32);
        ldsm4(b[1], bAddr[1] + kb * 32);
#pragma unroll
        for (int mt = 0; mt < 2; mt++)
#pragma unroll
            for (int np = 0; np < 2; np++) {
                mma16816(acc[mt][2 * np], a[mt], &b[np][0]);
                mma16816(acc[mt][2 * np + 1], a[mt], &b[np][2]);
            }
    }

    float b1v[8];
#pragma unroll
    for (int nt = 0; nt < 4; nt++) {
        b1v[2 * nt] = (hb == 0) ? b1[C0 + 8 * nt + 2 * t] : 0.f;
        b1v[2 * nt + 1] = (hb == 0) ? b1[C0 + 8 * nt + 2 * t + 1] : 0.f;
    }

    float ps[4] = {0.f, 0.f, 0.f, 0.f};
    uint32_t* outw = (uint32_t*)g_hAB;
#pragma unroll
    for (int mt = 0; mt < 2; mt++)
#pragma unroll
        for (int nt = 0; nt < 4; nt++) {
            float v0 = acc[mt][nt][0] + b1v[2 * nt];
            float v1 = acc[mt][nt][1] + b1v[2 * nt + 1];
            float v2 = acc[mt][nt][2] + b1v[2 * nt];
            float v3 = acc[mt][nt][3] + b1v[2 * nt + 1];
            ps[2 * mt] += v0 + v1;
            ps[2 * mt + 1] += v2 + v3;
            int node0 = nt0 + R0 + 16 * mt + g;
            int cc = C0 + 8 * nt + 2 * t;
            if (node0 < NNODES)
                outw[((size_t)node0 * 256 + (hb << 7) + cc) >> 1] = packbf(v0, v1);
            if (node0 + 8 < NNODES)
                outw[((size_t)(node0 + 8) * 256 + (hb << 7) + cc) >> 1] = packbf(v2, v3);
        }
#pragma unroll
    for (int rl = 0; rl < 4; rl++) {
        ps[rl] += __shfl_xor_sync(0xffffffffu, ps[rl], 1);
        ps[rl] += __shfl_xor_sync(0xffffffffu, ps[rl], 2);
    }
    if (t == 0) {
#pragma unroll
        for (int rl = 0; rl < 4; rl++) {
            int row = R0 + 16 * (rl >> 1) + 8 * (rl & 1) + g;
            part[row * 4 + wc] = ps[rl];
        }
    }
    __syncthreads();
    if (tid < 64) {
        int node = nt0 + tid;
        if (node < NNODES) {
            float s = part[tid * 4] + part[tid * 4 + 1] + part[tid * 4 + 2] + part[tid * 4 + 3];
            if (hb == 0) g_sA[node] = s; else g_sB[node] = s;
        }
    }
}

// ---------------------------------------------------------------------------
// edge kernel, cp.async-pipelined, 2 CTAs/SM
// ---------------------------------------------------------------------------
#define OFF_XA   0
#define OFF_W2   17408
#define OFF_W3   52224
#define OFF_RAW  56576          // 64 x 512B raw gather
#define OFF_X3   89344          // 2 x 4352B
#define OFF_CD   98048          // 2 x 2304B
#define OFF_PART 102656         // 2048B
#define OFF_PAR  104704         // params
#define EDGE_SMEM 107904

__global__ void __launch_bounds__(256, 2)
edge_kernel(const float* __restrict__ W1, const float* __restrict__ g1,
            const float* __restrict__ be1,
            const float* __restrict__ W2, const float* __restrict__ b2,
            const float* __restrict__ g2, const float* __restrict__ be2,
            const float* __restrict__ W3,
            const int* __restrict__ rowI, const int* __restrict__ colI,
            const float* __restrict__ edge_attr, const float* __restrict__ edge_mask,
            const float* __restrict__ coord_diff) {
    extern __shared__ unsigned char sm[];
    unsigned char* smXA = sm + OFF_XA;                 // 64 x 272B (X1, then X2)
    uint32_t* XAw = (uint32_t*)smXA;
    unsigned char* smW2 = sm + OFF_W2;                 // 128 x 272B
    __nv_bfloat16* W2h = (__nv_bfloat16*)smW2;
    __nv_bfloat16* W3h = (__nv_bfloat16*)(sm + OFF_W3);
    unsigned char* smRaw = sm + OFF_RAW;               // 64 x 512B
    float* X3s = (float*)(sm + OFF_X3);                // 2 x (64 x 17 f32)
    float* cds = (float*)(sm + OFF_CD);                // 2 x (576 f32)
    float* partp = (float*)(sm + OFF_PART);            // 64 x 8 f32
    float* par = (float*)(sm + OFF_PAR);
    float* sw1c = par;           float* sg1 = par + 128;  float* sbe1 = par + 256;
    float* sb2 = par + 384;      float* sg2 = par + 512;  float* sbe2 = par + 640;
    float* sSw = par + 768;

    const int tid = threadIdx.x;
    if (tid < 128) {
        sw1c[tid] = W1[256 * 128 + tid];
        sg1[tid] = g1[tid]; sbe1[tid] = be1[tid];
        sb2[tid] = b2[tid]; sg2[tid] = g2[tid]; sbe2[tid] = be2[tid];
    }
    for (int idx = tid; idx < 128 * 128; idx += 256) {
        int k = idx >> 7, n = idx & 127;
        W2h[n * 136 + k] = __float2bfloat16(W2[idx]);
    }
    for (int idx = tid; idx < 16 * 128; idx += 256) {
        int n = idx >> 7, k = idx & 127;
        W3h[n * 136 + k] = __float2bfloat16(n < 9 ? W3[k * 9 + n] : 0.f);
    }
    __syncthreads();

    const int warp = tid >> 5, lane = tid & 31;
    const int lr = lane & 7, sel = lane >> 3, g = lane >> 2, t = lane & 3;
    const int R0 = (warp & 1) * 32, wc = warp >> 1, C0 = wc * 32;
    const int j0 = lane * 4;

    if (warp == 0) {
        float s = sw1c[lane] + sw1c[lane + 32] + sw1c[lane + 64] + sw1c[lane + 96];
#pragma unroll
        for (int o = 16; o > 0; o >>= 1) s += __shfl_xor_sync(0xffffffffu, s, o);
        if (lane == 0) sSw[0] = s;
    }
    __syncthreads();

    float w1v[4], g1v[4], be1v[4];
#pragma unroll
    for (int u = 0; u < 4; u++) {
        w1v[u] = sw1c[j0 + u]; g1v[u] = sg1[j0 + u]; be1v[u] = sbe1[j0 + u];
    }
    const float Sw = sSw[0];

    // ldmatrix base addresses
    uint32_t aAddr[2], bAddr[2];
#pragma unroll
    for (int mt = 0; mt < 2; mt++)
        aAddr[mt] = s2u(smXA + (R0 + 16 * mt + lr + (sel & 1) * 8) * 272 + (sel >> 1) * 16);
#pragma unroll
    for (int np = 0; np < 2; np++)
        bAddr[np] = s2u(smW2 + (C0 + 16 * np + lr + (sel >> 1) * 8) * 272 + (sel & 1) * 16);
    uint32_t aAddr2 = s2u(smXA + ((warp & 3) * 16 + lr + (sel & 1) * 8) * 272 + (sel >> 1) * 16);
    uint32_t bAddr3 = s2u(sm + OFF_W3 + (lr + (sel >> 1) * 8) * 272 + (sel & 1) * 16);

    const uint32_t rawBase = s2u(smRaw);
    const char* habBytes = (const char*)g_hAB;

    // prefetch lambda: stage tile's hAB gather into raw via cp.async
    auto prefetch = [&](int t_) {
        const int e0 = t_ * MTILE + warp * 8;
#pragma unroll
        for (int it = 0; it < 8; it++) {
            int e = e0 + it;
            int r = __ldg(rowI + e);
            int c = __ldg(colI + e);
            const char* src = (lane < 16)
                ? habBytes + (size_t)r * 512 + lane * 16
                : habBytes + (size_t)c * 512 + 256 + (lane - 16) * 16;
            cpa16(rawBase + (warp * 8 + it) * 512 + lane * 16, src);
        }
        asm volatile("cp.async.commit_group;" ::: "memory");
    };

    int p = 0;
    int prev = -1;
    const int tile0 = blockIdx.x;
    if (tile0 < NTILES) prefetch(tile0);

    for (int tile = tile0; tile < NTILES; tile += EDGE_GRID) {
        const int ebase = tile * MTILE;
        const int e0 = ebase + warp * 8;

        asm volatile("cp.async.wait_group 0;" ::: "memory");
        __syncthreads();   // B1: raw(tile) ready; prev GEMM2/scatter done

        // ---- Stage A: raw -> LN1 -> SiLU -> XA (bf16) ----
        {
            int rs8[8], cs8[8];
#pragma unroll
            for (int it = 0; it < 8; it++) {
                rs8[it] = __ldg(rowI + e0 + it);
                cs8[it] = __ldg(colI + e0 + it);
            }
            float eas[8], sa8[8], sb8[8];
#pragma unroll
            for (int it = 0; it < 8; it++) {
                eas[it] = __ldg(edge_attr + e0 + it);
                sa8[it] = __ldg(g_sA + rs8[it]);
                sb8[it] = __ldg(g_sB + cs8[it]);
            }
#pragma unroll
            for (int it = 0; it < 8; it++) {
                int el = warp * 8 + it;
                uint2 wa = *(const uint2*)(smRaw + el * 512 + 8 * lane);
                uint2 wb = *(const uint2*)(smRaw + el * 512 + 256 + 8 * lane);
                float ea = eas[it];
                float2 a0 = unpackbf(wa.x), a1 = unpackbf(wa.y);
                float2 f0 = unpackbf(wb.x), f1 = unpackbf(wb.y);
                float x0 = a0.x + f0.x + ea * w1v[0];
                float x1 = a0.y + f0.y + ea * w1v[1];
                float x2 = a1.x + f1.x + ea * w1v[2];
                float x3 = a1.y + f1.y + ea * w1v[3];
                float q = x0 * x0 + x1 * x1 + x2 * x2 + x3 * x3;
#pragma unroll
                for (int o = 16; o > 0; o >>= 1) q += __shfl_xor_sync(0xffffffffu, q, o);
                float mean = (sa8[it] + sb8[it] + ea * Sw) * (1.f / 128.f);
                float var = q * (1.f / 128.f) - mean * mean;
                float rsv = rsqrtf(var + 1e-5f);
                float mrs = -mean * rsv;
                float y0 = silu_f(fmaf(fmaf(x0, rsv, mrs), g1v[0], be1v[0]));
                float y1 = silu_f(fmaf(fmaf(x1, rsv, mrs), g1v[1], be1v[1]));
                float y2 = silu_f(fmaf(fmaf(x2, rsv, mrs), g1v[2], be1v[2]));
                float y3 = silu_f(fmaf(fmaf(x3, rsv, mrs), g1v[3], be1v[3]));
                *(uint2*)&XAw[el * 68 + lane * 2] =
                    make_uint2(packbf(y0, y1), packbf(y2, y3));
            }
        }
        __syncthreads();   // B2: X1 ready; raw free for prefetch

        // issue prefetch for next tile (overlaps GEMM1/LN2/GEMM2)
        int next = tile + EDGE_GRID;
        if (next < NTILES) prefetch(next);

        // ---- GEMM1: acc = X1 @ W2 ----
        float acc[2][4][4];
#pragma unroll
        for (int mt = 0; mt < 2; mt++)
#pragma unroll
            for (int nt = 0; nt < 4; nt++)
#pragma unroll
                for (int u = 0; u < 4; u++) acc[mt][nt][u] = 0.f;
#pragma unroll
        for (int kb = 0; kb < 8; kb++) {
            uint32_t a[2][4], b[2][4];
            ldsm4(a[0], aAddr[0] + kb * 32);
            ldsm4(a[1], aAddr[1] + kb * 32);
            ldsm4(b[0], bAddr[0] + kb * 32);
            ldsm4(b[1], bAddr[1] + kb * 32);
#pragma unroll
            for (int mt = 0; mt < 2; mt++)
#pragma unroll
                for (int np = 0; np < 2; np++) {
                    mma16816(acc[mt][2 * np], a[mt], &b[np][0]);
                    mma16816(acc[mt][2 * np + 1], a[mt], &b[np][2]);
                }
        }
        // bias + per-row partial sums (for LN2)
        float ps[4] = {0.f, 0.f, 0.f, 0.f}, pq[4] = {0.f, 0.f, 0.f, 0.f};
#pragma unroll
        for (int mt = 0; mt < 2; mt++)
#pragma unroll
            for (int nt = 0; nt < 4; nt++) {
                float2 bb = *(const float2*)&sb2[C0 + 8 * nt + 2 * t];
                float v0 = acc[mt][nt][0] + bb.x;
                float v1 = acc[mt][nt][1] + bb.y;
                float v2 = acc[mt][nt][2] + bb.x;
                float v3 = acc[mt][nt][3] + bb.y;
                acc[mt][nt][0] = v0; acc[mt][nt][1] = v1;
                acc[mt][nt][2] = v2; acc[mt][nt][3] = v3;
                ps[2 * mt] += v0 + v1; pq[2 * mt] += v0 * v0 + v1 * v1;
                ps[2 * mt + 1] += v2 + v3; pq[2 * mt + 1] += v2 * v2 + v3 * v3;
            }
#pragma unroll
        for (int rl = 0; rl < 4; rl++) {
            ps[rl] += __shfl_xor_sync(0xffffffffu, ps[rl], 1);
            ps[rl] += __shfl_xor_sync(0xffffffffu, ps[rl], 2);
            pq[rl] += __shfl_xor_sync(0xffffffffu, pq[rl], 1);
            pq[rl] += __shfl_xor_sync(0xffffffffu, pq[rl], 2);
        }
        if (t == 0) {
#pragma unroll
            for (int rl = 0; rl < 4; rl++) {
                int row = R0 + 16 * (rl >> 1) + 8 * (rl & 1) + g;
                *(float2*)&partp[row * 8 + wc * 2] = make_float2(ps[rl], pq[rl]);
            }
        }
        __syncthreads();   // B3

        // ---- LN2 + SiLU from registers, write X2 (bf16) into XA ----
        float rsl[4], mrl[4];
#pragma unroll
        for (int rl = 0; rl < 4; rl++) {
            int row = R0 + 16 * (rl >> 1) + 8 * (rl & 1) + g;
            float4 pA = *(const float4*)&partp[row * 8];
            float4 pB = *(const float4*)&partp[row * 8 + 4];
            float s = pA.x + pA.z + pB.x + pB.z;
            float q = pA.y + pA.w + pB.y + pB.w;
            float mean = s * (1.f / 128.f);
            float var = q * (1.f / 128.f) - mean * mean;
            rsl[rl] = rsqrtf(var + 1e-5f);
            mrl[rl] = -mean * rsl[rl];
        }
#pragma unroll
        for (int mt = 0; mt < 2; mt++)
#pragma unroll
            for (int nt = 0; nt < 4; nt++) {
                int rl0 = 2 * mt, rl1 = 2 * mt + 1;
                float2 gg = *(const float2*)&sg2[C0 + 8 * nt + 2 * t];
                float2 ee = *(const float2*)&sbe2[C0 + 8 * nt + 2 * t];
                float y0 = silu_f(fmaf(fmaf(acc[mt][nt][0], rsl[rl0], mrl[rl0]), gg.x, ee.x));
                float y1 = silu_f(fmaf(fmaf(acc[mt][nt][1], rsl[rl0], mrl[rl0]), gg.y, ee.y));
                float y2 = silu_f(fmaf(fmaf(acc[mt][nt][2], rsl[rl1], mrl[rl1]), gg.x, ee.x));
                float y3 = silu_f(fmaf(fmaf(acc[mt][nt][3], rsl[rl1], mrl[rl1]), gg.y, ee.y));
                int row = R0 + 16 * mt + g;
                int cw = (C0 + 8 * nt + 2 * t) >> 1;
                XAw[row * 68 + cw] = packbf(y0, y1);
                XAw[(row + 8) * 68 + cw] = packbf(y2, y3);
            }
        __syncthreads();   // B4

        // ---- GEMM2 (w0-3) | cd stage (w6-7) | deferred scatter of prev (w4-5) ----
        if (warp < 4) {
            float a2[2][4];
#pragma unroll
            for (int nt = 0; nt < 2; nt++)
#pragma unroll
                for (int u = 0; u < 4; u++) a2[nt][u] = 0.f;
#pragma unroll
            for (int kb = 0; kb < 8; kb++) {
                uint32_t aa[4], bb[4];
                ldsm4(aa, aAddr2 + kb * 32);
                ldsm4(bb, bAddr3 + kb * 32);
                mma16816(a2[0], aa, &bb[0]);
                mma16816(a2[1], aa, &bb[2]);
            }
            float* X3c = X3s + p * 1088;
            int row = warp * 16 + g;
#pragma unroll
            for (int nt = 0; nt < 2; nt++) {
                int cc = 8 * nt + 2 * t;
                X3c[row * 17 + cc] = a2[nt][0];
                X3c[row * 17 + cc + 1] = a2[nt][1];
                X3c[(row + 8) * 17 + cc] = a2[nt][2];
                X3c[(row + 8) * 17 + cc + 1] = a2[nt][3];
            }
        } else if (warp >= 6) {
            int el2 = tid - 192;
            float* cdc = cds + p * 576;
            const float* cdflat = coord_diff + (size_t)ebase * 9;
#pragma unroll
            for (int c9 = 0; c9 < 9; c9++) {
                int i = el2 + 64 * c9;
                cdc[i] = __ldg(cdflat + i);
            }
        } else if (prev >= 0) {
            int el2 = tid - 128;
            int e2 = prev * MTILE + el2;
            int r2 = __ldg(rowI + e2);
            float em = __ldg(edge_mask + e2);
            const float* X3o = X3s + (p ^ 1) * 1088;
            const float* cdo = cds + (p ^ 1) * 576;
            float ph[9], cd[9];
#pragma unroll
            for (int c9 = 0; c9 < 9; c9++) ph[c9] = X3o[el2 * 17 + c9];
#pragma unroll
            for (int c9 = 0; c9 < 9; c9++) cd[c9] = cdo[el2 * 9 + c9];
            float* aggp = g_agg + (size_t)r2 * 9;
#pragma unroll
            for (int l = 0; l < 3; l++)
#pragma unroll
                for (int k = 0; k < 3; k++) {
                    float tr = cd[k] * ph[l] + cd[3 + k] * ph[3 + l] + cd[6 + k] * ph[6 + l];
                    atomicAdd(aggp + l * 3 + k, tr * em);
                }
        }
        prev = tile; p ^= 1;
    }

    // drain: scatter for the final tile
    __syncthreads();
    if (prev >= 0 && warp >= 4 && warp < 6) {
        int el2 = tid - 128;
        int e2 = prev * MTILE + el2;
        int r2 = __ldg(rowI + e2);
        float em = __ldg(edge_mask + e2);
        const float* X3o = X3s + (p ^ 1) * 1088;
        const float* cdo = cds + (p ^ 1) * 576;
        float ph[9], cd[9];
#pragma unroll
        for (int c9 = 0; c9 < 9; c9++) ph[c9] = X3o[el2 * 17 + c9];
#pragma unroll
        for (int c9 = 0; c9 < 9; c9++) cd[c9] = cdo[el2 * 9 + c9];
        float* aggp = g_agg + (size_t)r2 * 9;
#pragma unroll
        for (int l = 0; l < 3; l++)
#pragma unroll
            for (int k = 0; k < 3; k++) {
                float tr = cd[k] * ph[l] + cd[3 + k] * ph[3 + l] + cd[6 + k] * ph[6 + l];
                atomicAdd(aggp + l * 3 + k, tr * em);
            }
    }
}

__global__ void finalize_kernel(const float* __restrict__ coord,
                                const float* __restrict__ node_mask,
                                float* __restrict__ out) {
    int i = blockIdx.x * 256 + threadIdx.x;
    if (i < NNODES * 9) {
        out[i] = (coord[i] + g_agg[i] * 0.01f) * node_mask[i / 9];
    }
}

extern "C" void kernel_launch(void* const* d_in, const int* in_sizes, int n_in,
                              void* d_out, int out_size) {
    const float* h          = (const float*)d_in[0];
    const float* coord      = (const float*)d_in[1];
    const float* coord_diff = (const float*)d_in[2];
    const float* edge_attr  = (const float*)d_in[3];
    const float* edge_mask  = (const float*)d_in[4];
    const float* node_mask  = (const float*)d_in[5];
    const int*   rowI       = (const int*)d_in[6];
    const int*   colI       = (const int*)d_in[7];
    const float* W1  = (const float*)d_in[8];
    const float* b1  = (const float*)d_in[9];
    const float* g1  = (const float*)d_in[10];
    const float* be1 = (const float*)d_in[11];
    const float* W2  = (const float*)d_in[12];
    const float* b2  = (const float*)d_in[13];
    const float* g2  = (const float*)d_in[14];
    const float* be2 = (const float*)d_in[15];
    const float* W3  = (const float*)d_in[16];
    float* out = (float*)d_out;

    cudaFuncSetAttribute(hab_kernel, cudaFuncAttributeMaxDynamicSharedMemorySize, HAB_SMEM);
    cudaFuncSetAttribute(edge_kernel, cudaFuncAttributeMaxDynamicSharedMemorySize, EDGE_SMEM);

    prep_kernel<<<(NNODES * 9 + 255) / 256, 256>>>(W1);
    hab_kernel<<<dim3((NNODES + 63) / 64, 2), 256, HAB_SMEM>>>(h, b1);
    edge_kernel<<<EDGE_GRID, 256, EDGE_SMEM>>>(W1, g1, be1, W2, b2, g2, be2, W3,
                                               rowI, colI, edge_attr, edge_mask, coord_diff);
    finalize_kernel<<<(NNODES * 9 + 255) / 256, 256>>>(coord, node_mask, out);
}

// round 5
// speedup vs baseline: 1.2939x; 1.2939x over previous
#include <cuda_runtime.h>
#include <cuda_bf16.h>
#include <cuda_fp16.h>
#include <stdint.h>

#define NNODES 50000
#define NEDGES 800000
#define MTILE 64
#define NTILES (NEDGES / MTILE)   // 12500

// ---------------- scratch ----------------
__device__ __align__(128) __nv_bfloat16 g_hAB[(size_t)NNODES * 256];
__device__ __align__(128) __nv_bfloat16 g_W1T[2 * 128 * 128];
__device__ float g_sA[NNODES];
__device__ float g_sB[NNODES];
__device__ float g_agg[NNODES * 9];

// ---------------- helpers ----------------
static __device__ __forceinline__ uint32_t packbf(float a, float b) {
    __nv_bfloat162 h = __floats2bfloat162_rn(a, b);
    return *reinterpret_cast<uint32_t*>(&h);
}
static __device__ __forceinline__ float2 unpackbf(uint32_t u) {
    __nv_bfloat162 h; *reinterpret_cast<uint32_t*>(&h) = u;
    return __bfloat1622float2(h);
}
static __device__ __forceinline__ void mma16816(float* c, const uint32_t* a, const uint32_t* b) {
    asm volatile(
        "mma.sync.aligned.m16n8k16.row.col.f32.bf16.bf16.f32 "
        "{%0,%1,%2,%3}, {%4,%5,%6,%7}, {%8,%9}, {%0,%1,%2,%3};\n"
        : "+f"(c[0]), "+f"(c[1]), "+f"(c[2]), "+f"(c[3])
        : "r"(a[0]), "r"(a[1]), "r"(a[2]), "r"(a[3]), "r"(b[0]), "r"(b[1]));
}
static __device__ __forceinline__ void ldsm4(uint32_t* r, uint32_t addr) {
    asm volatile("ldmatrix.sync.aligned.m8n8.x4.shared.b16 {%0,%1,%2,%3}, [%4];"
        : "=r"(r[0]), "=r"(r[1]), "=r"(r[2]), "=r"(r[3]) : "r"(addr));
}
// silu(x) = h + h*tanh(h), h = x/2, tanh via MUFU f16x2 (1 MUFU per 2 scalars)
static __device__ __forceinline__ float2 silu2(float x0, float x1) {
    float h0 = 0.5f * x0, h1 = 0.5f * x1;
    __half2 hx = __floats2half2_rn(h0, h1);
    uint32_t hu = *reinterpret_cast<uint32_t*>(&hx);
    uint32_t tu;
    asm("tanh.approx.f16x2 %0, %1;" : "=r"(tu) : "r"(hu));
    __half2 th; *reinterpret_cast<uint32_t*>(&th) = tu;
    float2 tf = __half22float2(th);
    return make_float2(fmaf(h0, tf.x, h0), fmaf(h1, tf.y, h1));
}
static __device__ __forceinline__ uint32_t s2u(const void* p) {
    return (uint32_t)__cvta_generic_to_shared(p);
}

// ---------------------------------------------------------------------------
// prep: W1 -> bf16 transposed halves; zero agg
// ---------------------------------------------------------------------------
__global__ void prep_kernel(const float* __restrict__ W1) {
    int i = blockIdx.x * 256 + threadIdx.x;
    if (i < 2 * 128 * 128) {
        int hb = i >> 14, n = (i >> 7) & 127, k = i & 127;
        g_W1T[i] = __float2bfloat16(W1[(size_t)(hb * 128 + k) * 128 + n]);
    }
    if (i < NNODES * 9) g_agg[i] = 0.f;
}

// ---------------------------------------------------------------------------
// hab: hA' = h @ W1[0:128] + b1 ; hB = h @ W1[128:256]; row sums to g_sA/g_sB
// ---------------------------------------------------------------------------
#define HAB_SMEM (17408 + 34816 + 1024)
__global__ void __launch_bounds__(256, 2)
hab_kernel(const float* __restrict__ h, const float* __restrict__ b1) {
    extern __shared__ unsigned char sm[];
    unsigned char* smA = sm;             // 64 x 272B
    unsigned char* smB = sm + 17408;     // 128 x 272B
    float* part = (float*)(sm + 52224);  // 64 x 4 floats

    const int tid = threadIdx.x;
    const int nt0 = blockIdx.x * 64;
    const int hb = blockIdx.y;

    for (int idx = tid; idx < 64 * 32; idx += 256) {
        int i = idx >> 5, kq = idx & 31;
        float4 v = make_float4(0.f, 0.f, 0.f, 0.f);
        if (nt0 + i < NNODES) v = *(const float4*)(h + (size_t)(nt0 + i) * 128 + kq * 4);
        *(uint2*)(smA + i * 272 + kq * 8) = make_uint2(packbf(v.x, v.y), packbf(v.z, v.w));
    }
    const uint4* w1src = (const uint4*)(g_W1T + (hb << 14));
    for (int idx = tid; idx < 128 * 16; idx += 256) {
        int n = idx >> 4, q = idx & 15;
        *(uint4*)(smB + n * 272 + q * 16) = w1src[idx];
    }
    __syncthreads();

    const int warp = tid >> 5, lane = tid & 31;
    const int lr = lane & 7, sel = lane >> 3, g = lane >> 2, t = lane & 3;
    const int R0 = (warp & 1) * 32, wc = warp >> 1, C0 = wc * 32;

    uint32_t aAddr[2], bAddr[2];
#pragma unroll
    for (int mt = 0; mt < 2; mt++)
        aAddr[mt] = s2u(smA + (R0 + 16 * mt + lr + (sel & 1) * 8) * 272 + (sel >> 1) * 16);
#pragma unroll
    for (int np = 0; np < 2; np++)
        bAddr[np] = s2u(smB + (C0 + 16 * np + lr + (sel >> 1) * 8) * 272 + (sel & 1) * 16);

    float acc[2][4][4];
#pragma unroll
    for (int mt = 0; mt < 2; mt++)
#pragma unroll
        for (int nt = 0; nt < 4; nt++)
#pragma unroll
            for (int u = 0; u < 4; u++) acc[mt][nt][u] = 0.f;

#pragma unroll
    for (int kb = 0; kb < 8; kb++) {
        uint32_t a[2][4], b[2][4];
        ldsm4(a[0], aAddr[0] + kb * 32);
        ldsm4(a[1], aAddr[1] + kb * 32);
        ldsm4(b[0], bAddr[0] + kb * 32);
        ldsm4(b[1], bAddr[1] + kb * 32);
#pragma unroll
        for (int mt = 0; mt < 2; mt++)
#pragma unroll
            for (int np = 0; np < 2; np++) {
                mma16816(acc[mt][2 * np], a[mt], &b[np][0]);
                mma16816(acc[mt][2 * np + 1], a[mt], &b[np][2]);
            }
    }

    float b1v[8];
#pragma unroll
    for (int nt = 0; nt < 4; nt++) {
        b1v[2 * nt] = (hb == 0) ? b1[C0 + 8 * nt + 2 * t] : 0.f;
        b1v[2 * nt + 1] = (hb == 0) ? b1[C0 + 8 * nt + 2 * t + 1] : 0.f;
    }

    float ps[4] = {0.f, 0.f, 0.f, 0.f};
    uint32_t* outw = (uint32_t*)g_hAB;
#pragma unroll
    for (int mt = 0; mt < 2; mt++)
#pragma unroll
        for (int nt = 0; nt < 4; nt++) {
            float v0 = acc[mt][nt][0] + b1v[2 * nt];
            float v1 = acc[mt][nt][1] + b1v[2 * nt + 1];
            float v2 = acc[mt][nt][2] + b1v[2 * nt];
            float v3 = acc[mt][nt][3] + b1v[2 * nt + 1];
            ps[2 * mt] += v0 + v1;
            ps[2 * mt + 1] += v2 + v3;
            int node0 = nt0 + R0 + 16 * mt + g;
            int cc = C0 + 8 * nt + 2 * t;
            if (node0 < NNODES)
                outw[((size_t)node0 * 256 + (hb << 7) + cc) >> 1] = packbf(v0, v1);
            if (node0 + 8 < NNODES)
                outw[((size_t)(node0 + 8) * 256 + (hb << 7) + cc) >> 1] = packbf(v2, v3);
        }
#pragma unroll
    for (int rl = 0; rl < 4; rl++) {
        ps[rl] += __shfl_xor_sync(0xffffffffu, ps[rl], 1);
        ps[rl] += __shfl_xor_sync(0xffffffffu, ps[rl], 2);
    }
    if (t == 0) {
#pragma unroll
        for (int rl = 0; rl < 4; rl++) {
            int row = R0 + 16 * (rl >> 1) + 8 * (rl & 1) + g;
            part[row * 4 + wc] = ps[rl];
        }
    }
    __syncthreads();
    if (tid < 64) {
        int node = nt0 + tid;
        if (node < NNODES) {
            float s = part[tid * 4] + part[tid * 4 + 1] + part[tid * 4 + 2] + part[tid * 4 + 3];
            if (hb == 0) g_sA[node] = s; else g_sB[node] = s;
        }
    }
}

// ---------------------------------------------------------------------------
// edge kernel (round-3 structure, occ 3) + f16x2-tanh silu
// ---------------------------------------------------------------------------
#define OFF_XA   0
#define OFF_W2   17408
#define OFF_W3   52224
#define OFF_X3   56576
#define OFF_PART 60928
#define OFF_CD   62976
#define OFF_PAR  66304
#define EDGE_SMEM 69440

__global__ void __launch_bounds__(256, 3)
edge_kernel(const float* __restrict__ W1, const float* __restrict__ g1,
            const float* __restrict__ be1,
            const float* __restrict__ W2, const float* __restrict__ b2,
            const float* __restrict__ g2, const float* __restrict__ be2,
            const float* __restrict__ W3,
            const int* __restrict__ rowI, const int* __restrict__ colI,
            const float* __restrict__ edge_attr, const float* __restrict__ edge_mask,
            const float* __restrict__ coord_diff) {
    extern __shared__ unsigned char sm[];
    unsigned char* smXA = sm + OFF_XA;                 // 64 x 272B (X1, then X2)
    uint32_t* XAw = (uint32_t*)smXA;
    unsigned char* smW2 = sm + OFF_W2;                 // 128 x 272B
    __nv_bfloat16* W2h = (__nv_bfloat16*)smW2;
    __nv_bfloat16* W3h = (__nv_bfloat16*)(sm + OFF_W3);
    float* X3s = (float*)(sm + OFF_X3);                // 64 x 17 f32
    float* partp = (float*)(sm + OFF_PART);            // 64 rows x 4 float2
    float* cds = (float*)(sm + OFF_CD);                // 64 x 13 f32
    float* par = (float*)(sm + OFF_PAR);
    float* sw1c = par;           float* sg1 = par + 128;  float* sbe1 = par + 256;
    float* sb2 = par + 384;      float* sg2 = par + 512;  float* sbe2 = par + 640;
    float* sSw = par + 768;

    const int tid = threadIdx.x;
    if (tid < 128) {
        sw1c[tid] = W1[256 * 128 + tid];
        sg1[tid] = g1[tid]; sbe1[tid] = be1[tid];
        sb2[tid] = b2[tid]; sg2[tid] = g2[tid]; sbe2[tid] = be2[tid];
    }
    for (int idx = tid; idx < 128 * 128; idx += 256) {
        int k = idx >> 7, n = idx & 127;
        W2h[n * 136 + k] = __float2bfloat16(W2[idx]);
    }
    for (int idx = tid; idx < 16 * 128; idx += 256) {
        int n = idx >> 7, k = idx & 127;
        W3h[n * 136 + k] = __float2bfloat16(n < 9 ? W3[k * 9 + n] : 0.f);
    }
    __syncthreads();

    const int warp = tid >> 5, lane = tid & 31;
    const int lr = lane & 7, sel = lane >> 3, g = lane >> 2, t = lane & 3;
    const int R0 = (warp & 1) * 32, wc = warp >> 1, C0 = wc * 32;
    const int j0 = lane * 4;

    if (warp == 0) {
        float s = sw1c[lane] + sw1c[lane + 32] + sw1c[lane + 64] + sw1c[lane + 96];
#pragma unroll
        for (int o = 16; o > 0; o >>= 1) s += __shfl_xor_sync(0xffffffffu, s, o);
        if (lane == 0) sSw[0] = s;
    }
    __syncthreads();

    float w1v[4], g1v[4], be1v[4];
#pragma unroll
    for (int u = 0; u < 4; u++) {
        w1v[u] = sw1c[j0 + u]; g1v[u] = sg1[j0 + u]; be1v[u] = sbe1[j0 + u];
    }
    const float Sw = sSw[0];

    // ldmatrix base addresses
    uint32_t aAddr[2], bAddr[2];
#pragma unroll
    for (int mt = 0; mt < 2; mt++)
        aAddr[mt] = s2u(smXA + (R0 + 16 * mt + lr + (sel & 1) * 8) * 272 + (sel >> 1) * 16);
#pragma unroll
    for (int np = 0; np < 2; np++)
        bAddr[np] = s2u(smW2 + (C0 + 16 * np + lr + (sel >> 1) * 8) * 272 + (sel & 1) * 16);
    uint32_t aAddr2 = s2u(smXA + ((warp & 3) * 16 + lr + (sel & 1) * 8) * 272 + (sel >> 1) * 16);
    uint32_t bAddr3 = s2u(sm + OFF_W3 + (lr + (sel >> 1) * 8) * 272 + (sel & 1) * 16);

    for (int tile = blockIdx.x; tile < NTILES; tile += gridDim.x) {
        const int ebase = tile * MTILE;
        const int e0 = ebase + warp * 8;

        // ---- Stage A: gather + LN1 + SiLU -> XA (bf16), depth-3 pipeline ----
        int rs8[8], cs8[8]; float eas[8];
#pragma unroll
        for (int it = 0; it < 8; it++) {
            rs8[it] = __ldg(rowI + e0 + it);
            cs8[it] = __ldg(colI + e0 + it);
            eas[it] = __ldg(edge_attr + e0 + it);
        }
        uint2 pwa[3], pwb[3]; float psa[3], psb[3];
#pragma unroll
        for (int p = 0; p < 3; p++) {
            pwa[p] = *(const uint2*)(g_hAB + (size_t)rs8[p] * 256 + j0);
            pwb[p] = *(const uint2*)(g_hAB + (size_t)cs8[p] * 256 + 128 + j0);
            psa[p] = __ldg(g_sA + rs8[p]);
            psb[p] = __ldg(g_sB + cs8[p]);
        }
#pragma unroll
        for (int it = 0; it < 8; it++) {
            const int s = it % 3;
            uint2 wa = pwa[s], wb = pwb[s];
            float sums = psa[s] + psb[s];
            float ea = eas[it];
            if (it + 3 < 8) {
                pwa[s] = *(const uint2*)(g_hAB + (size_t)rs8[it + 3] * 256 + j0);
                pwb[s] = *(const uint2*)(g_hAB + (size_t)cs8[it + 3] * 256 + 128 + j0);
                psa[s] = __ldg(g_sA + rs8[it + 3]);
                psb[s] = __ldg(g_sB + cs8[it + 3]);
            }
            float2 a0 = unpackbf(wa.x), a1 = unpackbf(wa.y);
            float2 f0 = unpackbf(wb.x), f1 = unpackbf(wb.y);
            float x0 = a0.x + f0.x + ea * w1v[0];
            float x1 = a0.y + f0.y + ea * w1v[1];
            float x2 = a1.x + f1.x + ea * w1v[2];
            float x3 = a1.y + f1.y + ea * w1v[3];
            float q = x0 * x0 + x1 * x1 + x2 * x2 + x3 * x3;
#pragma unroll
            for (int o = 16; o > 0; o >>= 1) q += __shfl_xor_sync(0xffffffffu, q, o);
            float mean = (sums + ea * Sw) * (1.f / 128.f);
            float var = q * (1.f / 128.f) - mean * mean;
            float rsv = rsqrtf(var + 1e-5f);
            float mrs = -mean * rsv;
            float2 y01 = silu2(fmaf(fmaf(x0, rsv, mrs), g1v[0], be1v[0]),
                               fmaf(fmaf(x1, rsv, mrs), g1v[1], be1v[1]));
            float2 y23 = silu2(fmaf(fmaf(x2, rsv, mrs), g1v[2], be1v[2]),
                               fmaf(fmaf(x3, rsv, mrs), g1v[3], be1v[3]));
            *(uint2*)&XAw[(warp * 8 + it) * 68 + lane * 2] =
                make_uint2(packbf(y01.x, y01.y), packbf(y23.x, y23.y));
        }
        __syncthreads();   // sync1

        // ---- GEMM1: acc = X1 @ W2 ----
        float acc[2][4][4];
#pragma unroll
        for (int mt = 0; mt < 2; mt++)
#pragma unroll
            for (int nt = 0; nt < 4; nt++)
#pragma unroll
                for (int u = 0; u < 4; u++) acc[mt][nt][u] = 0.f;
#pragma unroll
        for (int kb = 0; kb < 8; kb++) {
            uint32_t a[2][4], b[2][4];
            ldsm4(a[0], aAddr[0] + kb * 32);
            ldsm4(a[1], aAddr[1] + kb * 32);
            ldsm4(b[0], bAddr[0] + kb * 32);
            ldsm4(b[1], bAddr[1] + kb * 32);
#pragma unroll
            for (int mt = 0; mt < 2; mt++)
#pragma unroll
                for (int np = 0; np < 2; np++) {
                    mma16816(acc[mt][2 * np], a[mt], &b[np][0]);
                    mma16816(acc[mt][2 * np + 1], a[mt], &b[np][2]);
                }
        }
        // bias + per-row partial sums (for LN2); params from smem
        float ps[4] = {0.f, 0.f, 0.f, 0.f}, pq[4] = {0.f, 0.f, 0.f, 0.f};
#pragma unroll
        for (int mt = 0; mt < 2; mt++)
#pragma unroll
            for (int nt = 0; nt < 4; nt++) {
                float2 bb = *(const float2*)&sb2[C0 + 8 * nt + 2 * t];
                float v0 = acc[mt][nt][0] + bb.x;
                float v1 = acc[mt][nt][1] + bb.y;
                float v2 = acc[mt][nt][2] + bb.x;
                float v3 = acc[mt][nt][3] + bb.y;
                acc[mt][nt][0] = v0; acc[mt][nt][1] = v1;
                acc[mt][nt][2] = v2; acc[mt][nt][3] = v3;
                ps[2 * mt] += v0 + v1; pq[2 * mt] += v0 * v0 + v1 * v1;
                ps[2 * mt + 1] += v2 + v3; pq[2 * mt + 1] += v2 * v2 + v3 * v3;
            }
#pragma unroll
        for (int rl = 0; rl < 4; rl++) {
            ps[rl] += __shfl_xor_sync(0xffffffffu, ps[rl], 1);
            ps[rl] += __shfl_xor_sync(0xffffffffu, ps[rl], 2);
            pq[rl] += __shfl_xor_sync(0xffffffffu, pq[rl], 1);
            pq[rl] += __shfl_xor_sync(0xffffffffu, pq[rl], 2);
        }
        if (t == 0) {
#pragma unroll
            for (int rl = 0; rl < 4; rl++) {
                int row = R0 + 16 * (rl >> 1) + 8 * (rl & 1) + g;
                *(float2*)&partp[row * 8 + wc * 2] = make_float2(ps[rl], pq[rl]);
            }
        }
        __syncthreads();   // sync2

        // ---- LN2 + SiLU from registers, write X2 (bf16) into XA ----
        float rsl[4], mrl[4];
#pragma unroll
        for (int rl = 0; rl < 4; rl++) {
            int row = R0 + 16 * (rl >> 1) + 8 * (rl & 1) + g;
            float4 pA = *(const float4*)&partp[row * 8];
            float4 pB = *(const float4*)&partp[row * 8 + 4];
            float s = pA.x + pA.z + pB.x + pB.z;
            float q = pA.y + pA.w + pB.y + pB.w;
            float mean = s * (1.f / 128.f);
            float var = q * (1.f / 128.f) - mean * mean;
            rsl[rl] = rsqrtf(var + 1e-5f);
            mrl[rl] = -mean * rsl[rl];
        }
#pragma unroll
        for (int mt = 0; mt < 2; mt++)
#pragma unroll
            for (int nt = 0; nt < 4; nt++) {
                int rl0 = 2 * mt, rl1 = 2 * mt + 1;
                float2 gg = *(const float2*)&sg2[C0 + 8 * nt + 2 * t];
                float2 ee = *(const float2*)&sbe2[C0 + 8 * nt + 2 * t];
                float2 y01 = silu2(fmaf(fmaf(acc[mt][nt][0], rsl[rl0], mrl[rl0]), gg.x, ee.x),
                                   fmaf(fmaf(acc[mt][nt][1], rsl[rl0], mrl[rl0]), gg.y, ee.y));
                float2 y23 = silu2(fmaf(fmaf(acc[mt][nt][2], rsl[rl1], mrl[rl1]), gg.x, ee.x),
                                   fmaf(fmaf(acc[mt][nt][3], rsl[rl1], mrl[rl1]), gg.y, ee.y));
                int row = R0 + 16 * mt + g;
                int cw = (C0 + 8 * nt + 2 * t) >> 1;
                XAw[row * 68 + cw] = packbf(y01.x, y01.y);
                XAw[(row + 8) * 68 + cw] = packbf(y23.x, y23.y);
            }
        __syncthreads();   // sync3

        // ---- GEMM2 (warps 0-3) + coord_diff staging (warps 4-5) ----
        if (warp < 4) {
            float a2[2][4];
#pragma unroll
            for (int nt = 0; nt < 2; nt++)
#pragma unroll
                for (int u = 0; u < 4; u++) a2[nt][u] = 0.f;
#pragma unroll
            for (int kb = 0; kb < 8; kb++) {
                uint32_t aa[4], bb[4];
                ldsm4(aa, aAddr2 + kb * 32);
                ldsm4(bb, bAddr3 + kb * 32);
                mma16816(a2[0], aa, &bb[0]);
                mma16816(a2[1], aa, &bb[2]);
            }
            int row = warp * 16 + g;
#pragma unroll
            for (int nt = 0; nt < 2; nt++) {
                int cc = 8 * nt + 2 * t;
                X3s[row * 17 + cc] = a2[nt][0];
                X3s[row * 17 + cc + 1] = a2[nt][1];
                X3s[(row + 8) * 17 + cc] = a2[nt][2];
                X3s[(row + 8) * 17 + cc + 1] = a2[nt][3];
            }
        } else if (warp < 6) {
            int el2 = tid - 128;
            const float* cdp = coord_diff + (size_t)(ebase + el2) * 9;
#pragma unroll
            for (int c9 = 0; c9 < 9; c9++) cds[el2 * 13 + c9] = __ldg(cdp + c9);
        }
        __syncthreads();   // sync4

        // ---- scatter (warps 4-5) ----
        if (warp >= 4 && warp < 6) {
            int el2 = tid - 128;
            int e2 = ebase + el2;
            int r2 = __ldg(rowI + e2);
            float em = __ldg(edge_mask + e2);
            float ph[9], cd[9];
#pragma unroll
            for (int c9 = 0; c9 < 9; c9++) ph[c9] = X3s[el2 * 17 + c9];
#pragma unroll
            for (int c9 = 0; c9 < 9; c9++) cd[c9] = cds[el2 * 13 + c9];
            float* aggp = g_agg + (size_t)r2 * 9;
#pragma unroll
            for (int l = 0; l < 3; l++)
#pragma unroll
                for (int k = 0; k < 3; k++) {
                    float tr = cd[k] * ph[l] + cd[3 + k] * ph[3 + l] + cd[6 + k] * ph[6 + l];
                    atomicAdd(aggp + l * 3 + k, tr * em);
                }
        }
    }
}

__global__ void finalize_kernel(const float* __restrict__ coord,
                                const float* __restrict__ node_mask,
                                float* __restrict__ out) {
    int i = blockIdx.x * 256 + threadIdx.x;
    if (i < NNODES * 9) {
        out[i] = (coord[i] + g_agg[i] * 0.01f) * node_mask[i / 9];
    }
}

extern "C" void kernel_launch(void* const* d_in, const int* in_sizes, int n_in,
                              void* d_out, int out_size) {
    const float* h          = (const float*)d_in[0];
    const float* coord      = (const float*)d_in[1];
    const float* coord_diff = (const float*)d_in[2];
    const float* edge_attr  = (const float*)d_in[3];
    const float* edge_mask  = (const float*)d_in[4];
    const float* node_mask  = (const float*)d_in[5];
    const int*   rowI       = (const int*)d_in[6];
    const int*   colI       = (const int*)d_in[7];
    const float* W1  = (const float*)d_in[8];
    const float* b1  = (const float*)d_in[9];
    const float* g1  = (const float*)d_in[10];
    const float* be1 = (const float*)d_in[11];
    const float* W2  = (const float*)d_in[12];
    const float* b2  = (const float*)d_in[13];
    const float* g2  = (const float*)d_in[14];
    const float* be2 = (const float*)d_in[15];
    const float* W3  = (const float*)d_in[16];
    float* out = (float*)d_out;

    cudaFuncSetAttribute(hab_kernel, cudaFuncAttributeMaxDynamicSharedMemorySize, HAB_SMEM);
    cudaFuncSetAttribute(edge_kernel, cudaFuncAttributeMaxDynamicSharedMemorySize, EDGE_SMEM);

    prep_kernel<<<(NNODES * 9 + 255) / 256, 256>>>(W1);
    hab_kernel<<<dim3((NNODES + 63) / 64, 2), 256, HAB_SMEM>>>(h, b1);
    edge_kernel<<<444, 256, EDGE_SMEM>>>(W1, g1, be1, W2, b2, g2, be2, W3,
                                         rowI, colI, edge_attr, edge_mask, coord_diff);
    finalize_kernel<<<(NNODES * 9 + 255) / 256, 256>>>(coord, node_mask, out);
}

// round 6
// speedup vs baseline: 1.3215x; 1.0213x over previous
#include <cuda_runtime.h>
#include <cuda_bf16.h>
#include <cuda_fp16.h>
#include <stdint.h>

#define NNODES 50000
#define NEDGES 800000
#define MTILE 64
#define NTILES (NEDGES / MTILE)   // 12500

typedef unsigned long long ull;

// ---------------- scratch ----------------
__device__ __align__(128) __nv_bfloat16 g_hAB[(size_t)NNODES * 256];
__device__ __align__(128) __nv_bfloat16 g_W1T[2 * 128 * 128];
__device__ float g_sA[NNODES];
__device__ float g_sB[NNODES];
__device__ float g_agg[NNODES * 9];

// ---------------- helpers ----------------
static __device__ __forceinline__ uint32_t packbf(float a, float b) {
    __nv_bfloat162 h = __floats2bfloat162_rn(a, b);
    return *reinterpret_cast<uint32_t*>(&h);
}
static __device__ __forceinline__ float2 unpackbf(uint32_t u) {
    __nv_bfloat162 h; *reinterpret_cast<uint32_t*>(&h) = u;
    return __bfloat1622float2(h);
}
// ---- packed f32x2 ----
static __device__ __forceinline__ ull pk2(float lo, float hi) {
    ull r; asm("mov.b64 %0, {%1, %2};" : "=l"(r) : "f"(lo), "f"(hi)); return r;
}
static __device__ __forceinline__ float2 up2(ull v) {
    float2 f; asm("mov.b64 {%0, %1}, %2;" : "=f"(f.x), "=f"(f.y) : "l"(v)); return f;
}
static __device__ __forceinline__ ull add2(ull a, ull b) {
    ull r; asm("add.rn.f32x2 %0, %1, %2;" : "=l"(r) : "l"(a), "l"(b)); return r;
}
static __device__ __forceinline__ ull mul2(ull a, ull b) {
    ull r; asm("mul.rn.f32x2 %0, %1, %2;" : "=l"(r) : "l"(a), "l"(b)); return r;
}
static __device__ __forceinline__ ull fma2(ull a, ull b, ull c) {
    ull r; asm("fma.rn.f32x2 %0, %1, %2, %3;" : "=l"(r) : "l"(a), "l"(b), "l"(c)); return r;
}
// bf16x2 word -> f32x2 (element order preserved)
static __device__ __forceinline__ ull bf2f2(uint32_t u) {
    uint32_t lo = u << 16;
    uint32_t hi = u & 0xFFFF0000u;
    ull r; asm("mov.b64 %0, {%1, %2};" : "=l"(r) : "r"(lo), "r"(hi)); return r;
}

static __device__ __forceinline__ void mma16816(float* c, const uint32_t* a, const uint32_t* b) {
    asm volatile(
        "mma.sync.aligned.m16n8k16.row.col.f32.bf16.bf16.f32 "
        "{%0,%1,%2,%3}, {%4,%5,%6,%7}, {%8,%9}, {%0,%1,%2,%3};\n"
        : "+f"(c[0]), "+f"(c[1]), "+f"(c[2]), "+f"(c[3])
        : "r"(a[0]), "r"(a[1]), "r"(a[2]), "r"(a[3]), "r"(b[0]), "r"(b[1]));
}
static __device__ __forceinline__ void ldsm4(uint32_t* r, uint32_t addr) {
    asm volatile("ldmatrix.sync.aligned.m8n8.x4.shared.b16 {%0,%1,%2,%3}, [%4];"
        : "=r"(r[0]), "=r"(r[1]), "=r"(r[2]), "=r"(r[3]) : "r"(addr));
}
// silu(x) = h + h*tanh(h), h = x/2, tanh via MUFU f16x2 (1 MUFU per 2 scalars)
// packed form: input/output f32x2
static __device__ __forceinline__ ull silu2p(ull y2) {
    ull h2 = mul2(y2, 0x3F0000003F000000ull);  // (0.5f, 0.5f)
    float2 hf = up2(h2);
    __half2 hx = __floats2half2_rn(hf.x, hf.y);
    uint32_t hu = *reinterpret_cast<uint32_t*>(&hx);
    uint32_t tu;
    asm("tanh.approx.f16x2 %0, %1;" : "=r"(tu) : "r"(hu));
    __half2 th; *reinterpret_cast<uint32_t*>(&th) = tu;
    float2 tf = __half22float2(th);
    return fma2(h2, pk2(tf.x, tf.y), h2);
}
static __device__ __forceinline__ uint32_t s2u(const void* p) {
    return (uint32_t)__cvta_generic_to_shared(p);
}

// ---------------------------------------------------------------------------
// prep: W1 -> bf16 transposed halves; zero agg
// ---------------------------------------------------------------------------
__global__ void prep_kernel(const float* __restrict__ W1) {
    int i = blockIdx.x * 256 + threadIdx.x;
    if (i < 2 * 128 * 128) {
        int hb = i >> 14, n = (i >> 7) & 127, k = i & 127;
        g_W1T[i] = __float2bfloat16(W1[(size_t)(hb * 128 + k) * 128 + n]);
    }
    if (i < NNODES * 9) g_agg[i] = 0.f;
}

// ---------------------------------------------------------------------------
// hab: hA' = h @ W1[0:128] + b1 ; hB = h @ W1[128:256]; row sums to g_sA/g_sB
// ---------------------------------------------------------------------------
#define HAB_SMEM (17408 + 34816 + 1024)
__global__ void __launch_bounds__(256, 2)
hab_kernel(const float* __restrict__ h, const float* __restrict__ b1) {
    extern __shared__ unsigned char sm[];
    unsigned char* smA = sm;             // 64 x 272B
    unsigned char* smB = sm + 17408;     // 128 x 272B
    float* part = (float*)(sm + 52224);  // 64 x 4 floats

    const int tid = threadIdx.x;
    const int nt0 = blockIdx.x * 64;
    const int hb = blockIdx.y;

    for (int idx = tid; idx < 64 * 32; idx += 256) {
        int i = idx >> 5, kq = idx & 31;
        float4 v = make_float4(0.f, 0.f, 0.f, 0.f);
        if (nt0 + i < NNODES) v = *(const float4*)(h + (size_t)(nt0 + i) * 128 + kq * 4);
        *(uint2*)(smA + i * 272 + kq * 8) = make_uint2(packbf(v.x, v.y), packbf(v.z, v.w));
    }
    const uint4* w1src = (const uint4*)(g_W1T + (hb << 14));
    for (int idx = tid; idx < 128 * 16; idx += 256) {
        int n = idx >> 4, q = idx & 15;
        *(uint4*)(smB + n * 272 + q * 16) = w1src[idx];
    }
    __syncthreads();

    const int warp = tid >> 5, lane = tid & 31;
    const int lr = lane & 7, sel = lane >> 3, g = lane >> 2, t = lane & 3;
    const int R0 = (warp & 1) * 32, wc = warp >> 1, C0 = wc * 32;

    uint32_t aAddr[2], bAddr[2];
#pragma unroll
    for (int mt = 0; mt < 2; mt++)
        aAddr[mt] = s2u(smA + (R0 + 16 * mt + lr + (sel & 1) * 8) * 272 + (sel >> 1) * 16);
#pragma unroll
    for (int np = 0; np < 2; np++)
        bAddr[np] = s2u(smB + (C0 + 16 * np + lr + (sel >> 1) * 8) * 272 + (sel & 1) * 16);

    float acc[2][4][4];
#pragma unroll
    for (int mt = 0; mt < 2; mt++)
#pragma unroll
        for (int nt = 0; nt < 4; nt++)
#pragma unroll
            for (int u = 0; u < 4; u++) acc[mt][nt][u] = 0.f;

#pragma unroll
    for (int kb = 0; kb < 8; kb++) {
        uint32_t a[2][4], b[2][4];
        ldsm4(a[0], aAddr[0] + kb * 32);
        ldsm4(a[1], aAddr[1] + kb * 32);
        ldsm4(b[0], bAddr[0] + kb * 32);
        ldsm4(b[1], bAddr[1] + kb * 32);
#pragma unroll
        for (int mt = 0; mt < 2; mt++)
#pragma unroll
            for (int np = 0; np < 2; np++) {
                mma16816(acc[mt][2 * np], a[mt], &b[np][0]);
                mma16816(acc[mt][2 * np + 1], a[mt], &b[np][2]);
            }
    }

    float b1v[8];
#pragma unroll
    for (int nt = 0; nt < 4; nt++) {
        b1v[2 * nt] = (hb == 0) ? b1[C0 + 8 * nt + 2 * t] : 0.f;
        b1v[2 * nt + 1] = (hb == 0) ? b1[C0 + 8 * nt + 2 * t + 1] : 0.f;
    }

    float ps[4] = {0.f, 0.f, 0.f, 0.f};
    uint32_t* outw = (uint32_t*)g_hAB;
#pragma unroll
    for (int mt = 0; mt < 2; mt++)
#pragma unroll
        for (int nt = 0; nt < 4; nt++) {
            float v0 = acc[mt][nt][0] + b1v[2 * nt];
            float v1 = acc[mt][nt][1] + b1v[2 * nt + 1];
            float v2 = acc[mt][nt][2] + b1v[2 * nt];
            float v3 = acc[mt][nt][3] + b1v[2 * nt + 1];
            ps[2 * mt] += v0 + v1;
            ps[2 * mt + 1] += v2 + v3;
            int node0 = nt0 + R0 + 16 * mt + g;
            int cc = C0 + 8 * nt + 2 * t;
            if (node0 < NNODES)
                outw[((size_t)node0 * 256 + (hb << 7) + cc) >> 1] = packbf(v0, v1);
            if (node0 + 8 < NNODES)
                outw[((size_t)(node0 + 8) * 256 + (hb << 7) + cc) >> 1] = packbf(v2, v3);
        }
#pragma unroll
    for (int rl = 0; rl < 4; rl++) {
        ps[rl] += __shfl_xor_sync(0xffffffffu, ps[rl], 1);
        ps[rl] += __shfl_xor_sync(0xffffffffu, ps[rl], 2);
    }
    if (t == 0) {
#pragma unroll
        for (int rl = 0; rl < 4; rl++) {
            int row = R0 + 16 * (rl >> 1) + 8 * (rl & 1) + g;
            part[row * 4 + wc] = ps[rl];
        }
    }
    __syncthreads();
    if (tid < 64) {
        int node = nt0 + tid;
        if (node < NNODES) {
            float s = part[tid * 4] + part[tid * 4 + 1] + part[tid * 4 + 2] + part[tid * 4 + 3];
            if (hb == 0) g_sA[node] = s; else g_sB[node] = s;
        }
    }
}

// ---------------------------------------------------------------------------
// edge kernel (occ 3) + f16x2 silu + f32x2 packed scalar math
// ---------------------------------------------------------------------------
#define OFF_XA   0
#define OFF_W2   17408
#define OFF_W3   52224
#define OFF_X3   56576
#define OFF_PART 60928
#define OFF_CD   62976
#define OFF_PAR  66304
#define EDGE_SMEM 69440

__global__ void __launch_bounds__(256, 3)
edge_kernel(const float* __restrict__ W1, const float* __restrict__ g1,
            const float* __restrict__ be1,
            const float* __restrict__ W2, const float* __restrict__ b2,
            const float* __restrict__ g2, const float* __restrict__ be2,
            const float* __restrict__ W3,
            const int* __restrict__ rowI, const int* __restrict__ colI,
            const float* __restrict__ edge_attr, const float* __restrict__ edge_mask,
            const float* __restrict__ coord_diff) {
    extern __shared__ unsigned char sm[];
    unsigned char* smXA = sm + OFF_XA;                 // 64 x 272B (X1, then X2)
    uint32_t* XAw = (uint32_t*)smXA;
    unsigned char* smW2 = sm + OFF_W2;                 // 128 x 272B
    __nv_bfloat16* W2h = (__nv_bfloat16*)smW2;
    __nv_bfloat16* W3h = (__nv_bfloat16*)(sm + OFF_W3);
    float* X3s = (float*)(sm + OFF_X3);                // 64 x 17 f32
    float* partp = (float*)(sm + OFF_PART);            // 64 rows x 4 float2
    float* cds = (float*)(sm + OFF_CD);                // 64 x 13 f32
    float* par = (float*)(sm + OFF_PAR);
    float* sw1c = par;           float* sg1 = par + 128;  float* sbe1 = par + 256;
    float* sb2 = par + 384;      float* sg2 = par + 512;  float* sbe2 = par + 640;
    float* sSw = par + 768;

    const int tid = threadIdx.x;
    if (tid < 128) {
        sw1c[tid] = W1[256 * 128 + tid];
        sg1[tid] = g1[tid]; sbe1[tid] = be1[tid];
        sb2[tid] = b2[tid]; sg2[tid] = g2[tid]; sbe2[tid] = be2[tid];
    }
    for (int idx = tid; idx < 128 * 128; idx += 256) {
        int k = idx >> 7, n = idx & 127;
        W2h[n * 136 + k] = __float2bfloat16(W2[idx]);
    }
    for (int idx = tid; idx < 16 * 128; idx += 256) {
        int n = idx >> 7, k = idx & 127;
        W3h[n * 136 + k] = __float2bfloat16(n < 9 ? W3[k * 9 + n] : 0.f);
    }
    __syncthreads();

    const int warp = tid >> 5, lane = tid & 31;
    const int lr = lane & 7, sel = lane >> 3, g = lane >> 2, t = lane & 3;
    const int R0 = (warp & 1) * 32, wc = warp >> 1, C0 = wc * 32;
    const int j0 = lane * 4;

    if (warp == 0) {
        float s = sw1c[lane] + sw1c[lane + 32] + sw1c[lane + 64] + sw1c[lane + 96];
#pragma unroll
        for (int o = 16; o > 0; o >>= 1) s += __shfl_xor_sync(0xffffffffu, s, o);
        if (lane == 0) sSw[0] = s;
    }
    __syncthreads();

    // packed per-lane LN1 parameters
    const ull w01  = *(const ull*)&sw1c[j0],  w23  = *(const ull*)&sw1c[j0 + 2];
    const ull g01  = *(const ull*)&sg1[j0],   g23  = *(const ull*)&sg1[j0 + 2];
    const ull be01 = *(const ull*)&sbe1[j0],  be23 = *(const ull*)&sbe1[j0 + 2];
    const float Sw = sSw[0];

    // ldmatrix base addresses
    uint32_t aAddr[2], bAddr[2];
#pragma unroll
    for (int mt = 0; mt < 2; mt++)
        aAddr[mt] = s2u(smXA + (R0 + 16 * mt + lr + (sel & 1) * 8) * 272 + (sel >> 1) * 16);
#pragma unroll
    for (int np = 0; np < 2; np++)
        bAddr[np] = s2u(smW2 + (C0 + 16 * np + lr + (sel >> 1) * 8) * 272 + (sel & 1) * 16);
    uint32_t aAddr2 = s2u(smXA + ((warp & 3) * 16 + lr + (sel & 1) * 8) * 272 + (sel >> 1) * 16);
    uint32_t bAddr3 = s2u(sm + OFF_W3 + (lr + (sel >> 1) * 8) * 272 + (sel & 1) * 16);

    for (int tile = blockIdx.x; tile < NTILES; tile += gridDim.x) {
        const int ebase = tile * MTILE;
        const int e0 = ebase + warp * 8;

        // ---- Stage A: gather + LN1 + SiLU -> XA (bf16), depth-3 pipeline ----
        int rs8[8], cs8[8]; float eas[8];
#pragma unroll
        for (int it = 0; it < 8; it++) {
            rs8[it] = __ldg(rowI + e0 + it);
            cs8[it] = __ldg(colI + e0 + it);
            eas[it] = __ldg(edge_attr + e0 + it);
        }
        uint2 pwa[3], pwb[3]; float psa[3], psb[3];
#pragma unroll
        for (int p = 0; p < 3; p++) {
            pwa[p] = *(const uint2*)(g_hAB + (size_t)rs8[p] * 256 + j0);
            pwb[p] = *(const uint2*)(g_hAB + (size_t)cs8[p] * 256 + 128 + j0);
            psa[p] = __ldg(g_sA + rs8[p]);
            psb[p] = __ldg(g_sB + cs8[p]);
        }
#pragma unroll
        for (int it = 0; it < 8; it++) {
            const int s = it % 3;
            uint2 wa = pwa[s], wb = pwb[s];
            float sums = psa[s] + psb[s];
            float ea = eas[it];
            if (it + 3 < 8) {
                pwa[s] = *(const uint2*)(g_hAB + (size_t)rs8[it + 3] * 256 + j0);
                pwb[s] = *(const uint2*)(g_hAB + (size_t)cs8[it + 3] * 256 + 128 + j0);
                psa[s] = __ldg(g_sA + rs8[it + 3]);
                psb[s] = __ldg(g_sB + cs8[it + 3]);
            }
            ull a01 = bf2f2(wa.x), a23 = bf2f2(wa.y);
            ull f01 = bf2f2(wb.x), f23 = bf2f2(wb.y);
            ull ea2 = pk2(ea, ea);
            ull x01 = fma2(ea2, w01, add2(a01, f01));
            ull x23 = fma2(ea2, w23, add2(a23, f23));
            ull q2 = fma2(x01, x01, mul2(x23, x23));
            float2 qf = up2(q2);
            float q = qf.x + qf.y;
#pragma unroll
            for (int o = 16; o > 0; o >>= 1) q += __shfl_xor_sync(0xffffffffu, q, o);
            float mean = (sums + ea * Sw) * (1.f / 128.f);
            float var = q * (1.f / 128.f) - mean * mean;
            float rsv = rsqrtf(var + 1e-5f);
            float mrs = -mean * rsv;
            ull rsv2 = pk2(rsv, rsv), mrs2 = pk2(mrs, mrs);
            ull y01 = fma2(fma2(x01, rsv2, mrs2), g01, be01);
            ull y23 = fma2(fma2(x23, rsv2, mrs2), g23, be23);
            float2 s01 = up2(silu2p(y01));
            float2 s23 = up2(silu2p(y23));
            *(uint2*)&XAw[(warp * 8 + it) * 68 + lane * 2] =
                make_uint2(packbf(s01.x, s01.y), packbf(s23.x, s23.y));
        }
        __syncthreads();   // sync1

        // ---- GEMM1: acc = X1 @ W2 ----
        float acc[2][4][4];
#pragma unroll
        for (int mt = 0; mt < 2; mt++)
#pragma unroll
            for (int nt = 0; nt < 4; nt++)
#pragma unroll
                for (int u = 0; u < 4; u++) acc[mt][nt][u] = 0.f;
#pragma unroll
        for (int kb = 0; kb < 8; kb++) {
            uint32_t a[2][4], b[2][4];
            ldsm4(a[0], aAddr[0] + kb * 32);
            ldsm4(a[1], aAddr[1] + kb * 32);
            ldsm4(b[0], bAddr[0] + kb * 32);
            ldsm4(b[1], bAddr[1] + kb * 32);
#pragma unroll
            for (int mt = 0; mt < 2; mt++)
#pragma unroll
                for (int np = 0; np < 2; np++) {
                    mma16816(acc[mt][2 * np], a[mt], &b[np][0]);
                    mma16816(acc[mt][2 * np + 1], a[mt], &b[np][2]);
                }
        }
        // bias + per-row partial sums (for LN2), packed f32x2
        ull accp[2][4][2];
        ull psA[4], pqA[4];
#pragma unroll
        for (int rl = 0; rl < 4; rl++) { psA[rl] = 0ull; pqA[rl] = 0ull; }
#pragma unroll
        for (int mt = 0; mt < 2; mt++)
#pragma unroll
            for (int nt = 0; nt < 4; nt++) {
                ull bb = *(const ull*)&sb2[C0 + 8 * nt + 2 * t];
                ull v01 = add2(pk2(acc[mt][nt][0], acc[mt][nt][1]), bb);
                ull v23 = add2(pk2(acc[mt][nt][2], acc[mt][nt][3]), bb);
                accp[mt][nt][0] = v01; accp[mt][nt][1] = v23;
                psA[2 * mt] = add2(psA[2 * mt], v01);
                pqA[2 * mt] = fma2(v01, v01, pqA[2 * mt]);
                psA[2 * mt + 1] = add2(psA[2 * mt + 1], v23);
                pqA[2 * mt + 1] = fma2(v23, v23, pqA[2 * mt + 1]);
            }
        float ps[4], pq[4];
#pragma unroll
        for (int rl = 0; rl < 4; rl++) {
            float2 pf = up2(psA[rl]); ps[rl] = pf.x + pf.y;
            float2 qf = up2(pqA[rl]); pq[rl] = qf.x + qf.y;
            ps[rl] += __shfl_xor_sync(0xffffffffu, ps[rl], 1);
            ps[rl] += __shfl_xor_sync(0xffffffffu, ps[rl], 2);
            pq[rl] += __shfl_xor_sync(0xffffffffu, pq[rl], 1);
            pq[rl] += __shfl_xor_sync(0xffffffffu, pq[rl], 2);
        }
        if (t == 0) {
#pragma unroll
            for (int rl = 0; rl < 4; rl++) {
                int row = R0 + 16 * (rl >> 1) + 8 * (rl & 1) + g;
                *(float2*)&partp[row * 8 + wc * 2] = make_float2(ps[rl], pq[rl]);
            }
        }
        __syncthreads();   // sync2

        // ---- LN2 + SiLU from registers, write X2 (bf16) into XA ----
        ull rs2[4], mr2[4];
#pragma unroll
        for (int rl = 0; rl < 4; rl++) {
            int row = R0 + 16 * (rl >> 1) + 8 * (rl & 1) + g;
            float4 pA = *(const float4*)&partp[row * 8];
            float4 pB = *(const float4*)&partp[row * 8 + 4];
            float s = pA.x + pA.z + pB.x + pB.z;
            float q = pA.y + pA.w + pB.y + pB.w;
            float mean = s * (1.f / 128.f);
            float var = q * (1.f / 128.f) - mean * mean;
            float rsv = rsqrtf(var + 1e-5f);
            float mrs = -mean * rsv;
            rs2[rl] = pk2(rsv, rsv);
            mr2[rl] = pk2(mrs, mrs);
        }
#pragma unroll
        for (int mt = 0; mt < 2; mt++)
#pragma unroll
            for (int nt = 0; nt < 4; nt++) {
                int rl0 = 2 * mt, rl1 = 2 * mt + 1;
                ull gg = *(const ull*)&sg2[C0 + 8 * nt + 2 * t];
                ull ee = *(const ull*)&sbe2[C0 + 8 * nt + 2 * t];
                ull y01 = fma2(fma2(accp[mt][nt][0], rs2[rl0], mr2[rl0]), gg, ee);
                ull y23 = fma2(fma2(accp[mt][nt][1], rs2[rl1], mr2[rl1]), gg, ee);
                float2 s01 = up2(silu2p(y01));
                float2 s23 = up2(silu2p(y23));
                int row = R0 + 16 * mt + g;
                int cw = (C0 + 8 * nt + 2 * t) >> 1;
                XAw[row * 68 + cw] = packbf(s01.x, s01.y);
                XAw[(row + 8) * 68 + cw] = packbf(s23.x, s23.y);
            }
        __syncthreads();   // sync3

        // ---- GEMM2 (warps 0-3) + coord_diff staging (warps 4-5) ----
        if (warp < 4) {
            float a2[2][4];
#pragma unroll
            for (int nt = 0; nt < 2; nt++)
#pragma unroll
                for (int u = 0; u < 4; u++) a2[nt][u] = 0.f;
#pragma unroll
            for (int kb = 0; kb < 8; kb++) {
                uint32_t aa[4], bb[4];
                ldsm4(aa, aAddr2 + kb * 32);
                ldsm4(bb, bAddr3 + kb * 32);
                mma16816(a2[0], aa, &bb[0]);
                mma16816(a2[1], aa, &bb[2]);
            }
            int row = warp * 16 + g;
#pragma unroll
            for (int nt = 0; nt < 2; nt++) {
                int cc = 8 * nt + 2 * t;
                X3s[row * 17 + cc] = a2[nt][0];
                X3s[row * 17 + cc + 1] = a2[nt][1];
                X3s[(row + 8) * 17 + cc] = a2[nt][2];
                X3s[(row + 8) * 17 + cc + 1] = a2[nt][3];
            }
        } else if (warp < 6) {
            int el2 = tid - 128;
            const float* cdp = coord_diff + (size_t)(ebase + el2) * 9;
#pragma unroll
            for (int c9 = 0; c9 < 9; c9++) cds[el2 * 13 + c9] = __ldg(cdp + c9);
        }
        __syncthreads();   // sync4

        // ---- scatter (warps 4-5) ----
        if (warp >= 4 && warp < 6) {
            int el2 = tid - 128;
            int e2 = ebase + el2;
            int r2 = __ldg(rowI + e2);
            float em = __ldg(edge_mask + e2);
            float ph[9], cd[9];
#pragma unroll
            for (int c9 = 0; c9 < 9; c9++) ph[c9] = X3s[el2 * 17 + c9];
#pragma unroll
            for (int c9 = 0; c9 < 9; c9++) cd[c9] = cds[el2 * 13 + c9];
            float* aggp = g_agg + (size_t)r2 * 9;
#pragma unroll
            for (int l = 0; l < 3; l++)
#pragma unroll
                for (int k = 0; k < 3; k++) {
                    float tr = cd[k] * ph[l] + cd[3 + k] * ph[3 + l] + cd[6 + k] * ph[6 + l];
                    atomicAdd(aggp + l * 3 + k, tr * em);
                }
        }
    }
}

__global__ void finalize_kernel(const float* __restrict__ coord,
                                const float* __restrict__ node_mask,
                                float* __restrict__ out) {
    int i = blockIdx.x * 256 + threadIdx.x;
    if (i < NNODES * 9) {
        out[i] = (coord[i] + g_agg[i] * 0.01f) * node_mask[i / 9];
    }
}

extern "C" void kernel_launch(void* const* d_in, const int* in_sizes, int n_in,
                              void* d_out, int out_size) {
    const float* h          = (const float*)d_in[0];
    const float* coord      = (const float*)d_in[1];
    const float* coord_diff = (const float*)d_in[2];
    const float* edge_attr  = (const float*)d_in[3];
    const float* edge_mask  = (const float*)d_in[4];
    const float* node_mask  = (const float*)d_in[5];
    const int*   rowI       = (const int*)d_in[6];
    const int*   colI       = (const int*)d_in[7];
    const float* W1  = (const float*)d_in[8];
    const float* b1  = (const float*)d_in[9];
    const float* g1  = (const float*)d_in[10];
    const float* be1 = (const float*)d_in[11];
    const float* W2  = (const float*)d_in[12];
    const float* b2  = (const float*)d_in[13];
    const float* g2  = (const float*)d_in[14];
    const float* be2 = (const float*)d_in[15];
    const float* W3  = (const float*)d_in[16];
    float* out = (float*)d_out;

    cudaFuncSetAttribute(hab_kernel, cudaFuncAttributeMaxDynamicSharedMemorySize, HAB_SMEM);
    cudaFuncSetAttribute(edge_kernel, cudaFuncAttributeMaxDynamicSharedMemorySize, EDGE_SMEM);

    prep_kernel<<<(NNODES * 9 + 255) / 256, 256>>>(W1);
    hab_kernel<<<dim3((NNODES + 63) / 64, 2), 256, HAB_SMEM>>>(h, b1);
    edge_kernel<<<444, 256, EDGE_SMEM>>>(W1, g1, be1, W2, b2, g2, be2, W3,
                                         rowI, colI, edge_attr, edge_mask, coord_diff);
    finalize_kernel<<<(NNODES * 9 + 255) / 256, 256>>>(coord, node_mask, out);
}

// round 8
// speedup vs baseline: 1.3938x; 1.0547x over previous
#include <cuda_runtime.h>
#include <cuda_bf16.h>
#include <cuda_fp16.h>
#include <stdint.h>

#define NNODES 50000
#define NEDGES 800000
#define MTILE 64
#define NTILES (NEDGES / MTILE)   // 12500

typedef unsigned long long ull;

// ---------------- scratch ----------------
__device__ __align__(128) __nv_bfloat16 g_hAB[(size_t)NNODES * 256];
__device__ __align__(128) __nv_bfloat16 g_W1T[2 * 128 * 128];
__device__ float g_sA[NNODES];
__device__ float g_sB[NNODES];
__device__ float g_agg[NNODES * 9];

// ---------------- helpers ----------------
static __device__ __forceinline__ uint32_t packbf(float a, float b) {
    __nv_bfloat162 h = __floats2bfloat162_rn(a, b);
    return *reinterpret_cast<uint32_t*>(&h);
}
// ---- packed f32x2 ----
static __device__ __forceinline__ ull pk2(float lo, float hi) {
    ull r; asm("mov.b64 %0, {%1, %2};" : "=l"(r) : "f"(lo), "f"(hi)); return r;
}
static __device__ __forceinline__ float2 up2(ull v) {
    float2 f; asm("mov.b64 {%0, %1}, %2;" : "=f"(f.x), "=f"(f.y) : "l"(v)); return f;
}
static __device__ __forceinline__ ull add2(ull a, ull b) {
    ull r; asm("add.rn.f32x2 %0, %1, %2;" : "=l"(r) : "l"(a), "l"(b)); return r;
}
static __device__ __forceinline__ ull mul2(ull a, ull b) {
    ull r; asm("mul.rn.f32x2 %0, %1, %2;" : "=l"(r) : "l"(a), "l"(b)); return r;
}
static __device__ __forceinline__ ull fma2(ull a, ull b, ull c) {
    ull r; asm("fma.rn.f32x2 %0, %1, %2, %3;" : "=l"(r) : "l"(a), "l"(b), "l"(c)); return r;
}
// bf16x2 word -> f32x2 (element order preserved)
static __device__ __forceinline__ ull bf2f2(uint32_t u) {
    uint32_t lo = u << 16;
    uint32_t hi = u & 0xFFFF0000u;
    ull r; asm("mov.b64 %0, {%1, %2};" : "=l"(r) : "r"(lo), "r"(hi)); return r;
}

static __device__ __forceinline__ void mma16816(float* c, const uint32_t* a, const uint32_t* b) {
    asm volatile(
        "mma.sync.aligned.m16n8k16.row.col.f32.bf16.bf16.f32 "
        "{%0,%1,%2,%3}, {%4,%5,%6,%7}, {%8,%9}, {%0,%1,%2,%3};\n"
        : "+f"(c[0]), "+f"(c[1]), "+f"(c[2]), "+f"(c[3])
        : "r"(a[0]), "r"(a[1]), "r"(a[2]), "r"(a[3]), "r"(b[0]), "r"(b[1]));
}
static __device__ __forceinline__ void ldsm4(uint32_t* r, uint32_t addr) {
    asm volatile("ldmatrix.sync.aligned.m8n8.x4.shared.b16 {%0,%1,%2,%3}, [%4];"
        : "=r"(r[0]), "=r"(r[1]), "=r"(r[2]), "=r"(r[3]) : "r"(addr));
}
// silu(x) = h + h*tanh(h), h = x/2, tanh via MUFU f16x2; packed f32x2 in/out
static __device__ __forceinline__ ull silu2p(ull y2) {
    ull h2 = mul2(y2, 0x3F0000003F000000ull);  // (0.5f, 0.5f)
    float2 hf = up2(h2);
    __half2 hx = __floats2half2_rn(hf.x, hf.y);
    uint32_t hu = *reinterpret_cast<uint32_t*>(&hx);
    uint32_t tu;
    asm("tanh.approx.f16x2 %0, %1;" : "=r"(tu) : "r"(hu));
    __half2 th; *reinterpret_cast<uint32_t*>(&th) = tu;
    float2 tf = __half22float2(th);
    return fma2(h2, pk2(tf.x, tf.y), h2);
}
static __device__ __forceinline__ uint32_t s2u(const void* p) {
    return (uint32_t)__cvta_generic_to_shared(p);
}

// ---------------------------------------------------------------------------
// prep: W1 -> bf16 transposed halves; zero agg
// ---------------------------------------------------------------------------
__global__ void prep_kernel(const float* __restrict__ W1) {
    int i = blockIdx.x * 256 + threadIdx.x;
    if (i < 2 * 128 * 128) {
        int hb = i >> 14, n = (i >> 7) & 127, k = i & 127;
        g_W1T[i] = __float2bfloat16(W1[(size_t)(hb * 128 + k) * 128 + n]);
    }
    if (i < NNODES * 9) g_agg[i] = 0.f;
}

// ---------------------------------------------------------------------------
// hab: hA' = h @ W1[0:128] + b1 ; hB = h @ W1[128:256]; row sums to g_sA/g_sB
// ---------------------------------------------------------------------------
#define HAB_SMEM (17408 + 34816 + 1024)
__global__ void __launch_bounds__(256, 2)
hab_kernel(const float* __restrict__ h, const float* __restrict__ b1) {
    extern __shared__ unsigned char sm[];
    unsigned char* smA = sm;             // 64 x 272B
    unsigned char* smB = sm + 17408;     // 128 x 272B
    float* part = (float*)(sm + 52224);  // 64 x 4 floats

    const int tid = threadIdx.x;
    const int nt0 = blockIdx.x * 64;
    const int hb = blockIdx.y;

    for (int idx = tid; idx < 64 * 32; idx += 256) {
        int i = idx >> 5, kq = idx & 31;
        float4 v = make_float4(0.f, 0.f, 0.f, 0.f);
        if (nt0 + i < NNODES) v = *(const float4*)(h + (size_t)(nt0 + i) * 128 + kq * 4);
        *(uint2*)(smA + i * 272 + kq * 8) = make_uint2(packbf(v.x, v.y), packbf(v.z, v.w));
    }
    const uint4* w1src = (const uint4*)(g_W1T + (hb << 14));
    for (int idx = tid; idx < 128 * 16; idx += 256) {
        int n = idx >> 4, q = idx & 15;
        *(uint4*)(smB + n * 272 + q * 16) = w1src[idx];
    }
    __syncthreads();

    const int warp = tid >> 5, lane = tid & 31;
    const int lr = lane & 7, sel = lane >> 3, g = lane >> 2, t = lane & 3;
    const int R0 = (warp & 1) * 32, wc = warp >> 1, C0 = wc * 32;

    uint32_t aAddr[2], bAddr[2];
#pragma unroll
    for (int mt = 0; mt < 2; mt++)
        aAddr[mt] = s2u(smA + (R0 + 16 * mt + lr + (sel & 1) * 8) * 272 + (sel >> 1) * 16);
#pragma unroll
    for (int np = 0; np < 2; np++)
        bAddr[np] = s2u(smB + (C0 + 16 * np + lr + (sel >> 1) * 8) * 272 + (sel & 1) * 16);

    float acc[2][4][4];
#pragma unroll
    for (int mt = 0; mt < 2; mt++)
#pragma unroll
        for (int nt = 0; nt < 4; nt++)
#pragma unroll
            for (int u = 0; u < 4; u++) acc[mt][nt][u] = 0.f;

#pragma unroll
    for (int kb = 0; kb < 8; kb++) {
        uint32_t a[2][4], b[2][4];
        ldsm4(a[0], aAddr[0] + kb * 32);
        ldsm4(a[1], aAddr[1] + kb * 32);
        ldsm4(b[0], bAddr[0] + kb * 32);
        ldsm4(b[1], bAddr[1] + kb * 32);
#pragma unroll
        for (int mt = 0; mt < 2; mt++)
#pragma unroll
            for (int np = 0; np < 2; np++) {
                mma16816(acc[mt][2 * np], a[mt], &b[np][0]);
                mma16816(acc[mt][2 * np + 1], a[mt], &b[np][2]);
            }
    }

    float b1v[8];
#pragma unroll
    for (int nt = 0; nt < 4; nt++) {
        b1v[2 * nt] = (hb == 0) ? b1[C0 + 8 * nt + 2 * t] : 0.f;
        b1v[2 * nt + 1] = (hb == 0) ? b1[C0 + 8 * nt + 2 * t + 1] : 0.f;
    }

    float ps[4] = {0.f, 0.f, 0.f, 0.f};
    uint32_t* outw = (uint32_t*)g_hAB;
#pragma unroll
    for (int mt = 0; mt < 2; mt++)
#pragma unroll
        for (int nt = 0; nt < 4; nt++) {
            float v0 = acc[mt][nt][0] + b1v[2 * nt];
            float v1 = acc[mt][nt][1] + b1v[2 * nt + 1];
            float v2 = acc[mt][nt][2] + b1v[2 * nt];
            float v3 = acc[mt][nt][3] + b1v[2 * nt + 1];
            ps[2 * mt] += v0 + v1;
            ps[2 * mt + 1] += v2 + v3;
            int node0 = nt0 + R0 + 16 * mt + g;
            int cc = C0 + 8 * nt + 2 * t;
            if (node0 < NNODES)
                outw[((size_t)node0 * 256 + (hb << 7) + cc) >> 1] = packbf(v0, v1);
            if (node0 + 8 < NNODES)
                outw[((size_t)(node0 + 8) * 256 + (hb << 7) + cc) >> 1] = packbf(v2, v3);
        }
#pragma unroll
    for (int rl = 0; rl < 4; rl++) {
        ps[rl] += __shfl_xor_sync(0xffffffffu, ps[rl], 1);
        ps[rl] += __shfl_xor_sync(0xffffffffu, ps[rl], 2);
    }
    if (t == 0) {
#pragma unroll
        for (int rl = 0; rl < 4; rl++) {
            int row = R0 + 16 * (rl >> 1) + 8 * (rl & 1) + g;
            part[row * 4 + wc] = ps[rl];
        }
    }
    __syncthreads();
    if (tid < 64) {
        int node = nt0 + tid;
        if (node < NNODES) {
            float s = part[tid * 4] + part[tid * 4 + 1] + part[tid * 4 + 2] + part[tid * 4 + 3];
            if (hb == 0) g_sA[node] = s; else g_sB[node] = s;
        }
    }
}

// ---------------------------------------------------------------------------
// edge kernel (occ 3): 3-barrier pipeline, GEMM2 A-operand kept in registers
// ---------------------------------------------------------------------------
#define OFF_XA   0                 // 64 x 272B  (X1 only)
#define OFF_W2   17408             // 128 x 272B
#define OFF_W3   52224             // 16 x 272B
#define OFF_P3   56576             // 4 x 64 x 40B  X3 bf16 partials per warp-col
#define OFF_PART 66816             // 64 x 8 f32 (LN2 stats partials)
#define OFF_PAR  68864             // params
#define EDGE_SMEM 72512

__global__ void __launch_bounds__(256, 3)
edge_kernel(const float* __restrict__ W1, const float* __restrict__ g1,
            const float* __restrict__ be1,
            const float* __restrict__ W2, const float* __restrict__ b2,
            const float* __restrict__ g2, const float* __restrict__ be2,
            const float* __restrict__ W3,
            const int* __restrict__ rowI, const int* __restrict__ colI,
            const float* __restrict__ edge_attr, const float* __restrict__ edge_mask,
            const float* __restrict__ coord_diff) {
    extern __shared__ unsigned char sm[];
    unsigned char* smXA = sm + OFF_XA;
    uint32_t* XAw = (uint32_t*)smXA;
    __nv_bfloat16* W2h = (__nv_bfloat16*)(sm + OFF_W2);
    __nv_bfloat16* W3h = (__nv_bfloat16*)(sm + OFF_W3);
    uint32_t* P3w = (uint32_t*)(sm + OFF_P3);          // [wc][row][10 words]
    float* partp = (float*)(sm + OFF_PART);
    float* par = (float*)(sm + OFF_PAR);
    float* sw1c = par;           float* sg1 = par + 128;  float* sbe1 = par + 256;
    float* sb2 = par + 384;      float* sg2 = par + 512;  float* sbe2 = par + 640;
    float* sSw = par + 768;

    const int tid = threadIdx.x;
    if (tid < 128) {
        sw1c[tid] = W1[256 * 128 + tid];
        sg1[tid] = g1[tid]; sbe1[tid] = be1[tid];
        sb2[tid] = b2[tid]; sg2[tid] = g2[tid]; sbe2[tid] = be2[tid];
    }
    for (int idx = tid; idx < 128 * 128; idx += 256) {
        int k = idx >> 7, n = idx & 127;
        W2h[n * 136 + k] = __float2bfloat16(W2[idx]);
    }
    for (int idx = tid; idx < 16 * 128; idx += 256) {
        int n = idx >> 7, k = idx & 127;
        W3h[n * 136 + k] = __float2bfloat16(n < 9 ? W3[k * 9 + n] : 0.f);
    }
    __syncthreads();

    const int warp = tid >> 5, lane = tid & 31;
    const int lr = lane & 7, sel = lane >> 3, g = lane >> 2, t = lane & 3;
    const int R0 = (warp & 1) * 32, wc = warp >> 1, C0 = wc * 32;
    const int j0 = lane * 4;

    if (warp == 0) {
        float s = sw1c[lane] + sw1c[lane + 32] + sw1c[lane + 64] + sw1c[lane + 96];
#pragma unroll
        for (int o = 16; o > 0; o >>= 1) s += __shfl_xor_sync(0xffffffffu, s, o);
        if (lane == 0) sSw[0] = s;
    }
    __syncthreads();

    // packed per-lane LN1 parameters
    const ull w01  = *(const ull*)&sw1c[j0],  w23  = *(const ull*)&sw1c[j0 + 2];
    const ull g01  = *(const ull*)&sg1[j0],   g23  = *(const ull*)&sg1[j0 + 2];
    const ull be01 = *(const ull*)&sbe1[j0],  be23 = *(const ull*)&sbe1[j0 + 2];
    const float Sw = sSw[0];

    // ldmatrix base addresses
    uint32_t aAddr[2], bAddr[2];
#pragma unroll
    for (int mt = 0; mt < 2; mt++)
        aAddr[mt] = s2u(smXA + (R0 + 16 * mt + lr + (sel & 1) * 8) * 272 + (sel >> 1) * 16);
#pragma unroll
    for (int np = 0; np < 2; np++)
        bAddr[np] = s2u(sm + OFF_W2 + (C0 + 16 * np + lr + (sel >> 1) * 8) * 272 + (sel & 1) * 16);
    // W3 B-operand base: this warp's K-slice starts at col C0 -> byte 2*C0
    const uint32_t bAddr3 = s2u(sm + OFF_W3 + (lr + (sel >> 1) * 8) * 272 + (sel & 1) * 16) + wc * 64;

    for (int tile = blockIdx.x; tile < NTILES; tile += gridDim.x) {
        const int ebase = tile * MTILE;
        const int e0 = ebase + warp * 8;

        // ---- Stage A: gather + LN1 + SiLU -> XA (bf16), depth-3 pipeline ----
        int rs8[8], cs8[8]; float eas[8];
#pragma unroll
        for (int it = 0; it < 8; it++) {
            rs8[it] = __ldg(rowI + e0 + it);
            cs8[it] = __ldg(colI + e0 + it);
            eas[it] = __ldg(edge_attr + e0 + it);
        }
        uint2 pwa[3], pwb[3]; float psa[3], psb[3];
#pragma unroll
        for (int p = 0; p < 3; p++) {
            pwa[p] = *(const uint2*)(g_hAB + (size_t)rs8[p] * 256 + j0);
            pwb[p] = *(const uint2*)(g_hAB + (size_t)cs8[p] * 256 + 128 + j0);
            psa[p] = __ldg(g_sA + rs8[p]);
            psb[p] = __ldg(g_sB + cs8[p]);
        }
#pragma unroll
        for (int it = 0; it < 8; it++) {
            const int s = it % 3;
            uint2 wa = pwa[s], wb = pwb[s];
            float sums = psa[s] + psb[s];
            float ea = eas[it];
            if (it + 3 < 8) {
                pwa[s] = *(const uint2*)(g_hAB + (size_t)rs8[it + 3] * 256 + j0);
                pwb[s] = *(const uint2*)(g_hAB + (size_t)cs8[it + 3] * 256 + 128 + j0);
                psa[s] = __ldg(g_sA + rs8[it + 3]);
                psb[s] = __ldg(g_sB + cs8[it + 3]);
            }
            ull a01 = bf2f2(wa.x), a23 = bf2f2(wa.y);
            ull f01 = bf2f2(wb.x), f23 = bf2f2(wb.y);
            ull ea2 = pk2(ea, ea);
            ull x01 = fma2(ea2, w01, add2(a01, f01));
            ull x23 = fma2(ea2, w23, add2(a23, f23));
            ull q2 = fma2(x01, x01, mul2(x23, x23));
            float2 qf = up2(q2);
            float q = qf.x + qf.y;
#pragma unroll
            for (int o = 16; o > 0; o >>= 1) q += __shfl_xor_sync(0xffffffffu, q, o);
            float mean = (sums + ea * Sw) * (1.f / 128.f);
            float var = q * (1.f / 128.f) - mean * mean;
            float rsv = rsqrtf(var + 1e-5f);
            float mrs = -mean * rsv;
            ull rsv2 = pk2(rsv, rsv), mrs2 = pk2(mrs, mrs);
            ull y01 = fma2(fma2(x01, rsv2, mrs2), g01, be01);
            ull y23 = fma2(fma2(x23, rsv2, mrs2), g23, be23);
            float2 s01 = up2(silu2p(y01));
            float2 s23 = up2(silu2p(y23));
            *(uint2*)&XAw[(warp * 8 + it) * 68 + lane * 2] =
                make_uint2(packbf(s01.x, s01.y), packbf(s23.x, s23.y));
        }
        __syncthreads();   // sync1: X1 ready

        // ---- GEMM1: acc = X1 @ W2 ----
        float acc[2][4][4];
#pragma unroll
        for (int mt = 0; mt < 2; mt++)
#pragma unroll
            for (int nt = 0; nt < 4; nt++)
#pragma unroll
                for (int u = 0; u < 4; u++) acc[mt][nt][u] = 0.f;
#pragma unroll
        for (int kb = 0; kb < 8; kb++) {
            uint32_t a[2][4], b[2][4];
            ldsm4(a[0], aAddr[0] + kb * 32);
            ldsm4(a[1], aAddr[1] + kb * 32);
            ldsm4(b[0], bAddr[0] + kb * 32);
            ldsm4(b[1], bAddr[1] + kb * 32);
#pragma unroll
            for (int mt = 0; mt < 2; mt++)
#pragma unroll
                for (int np = 0; np < 2; np++) {
                    mma16816(acc[mt][2 * np], a[mt], &b[np][0]);
                    mma16816(acc[mt][2 * np + 1], a[mt], &b[np][2]);
                }
        }
        // bias + per-row partial sums (for LN2), packed f32x2
        ull accp[2][4][2];
        ull psA[4], pqA[4];
#pragma unroll
        for (int rl = 0; rl < 4; rl++) { psA[rl] = 0ull; pqA[rl] = 0ull; }
#pragma unroll
        for (int mt = 0; mt < 2; mt++)
#pragma unroll
            for (int nt = 0; nt < 4; nt++) {
                ull bb = *(const ull*)&sb2[C0 + 8 * nt + 2 * t];
                ull v01 = add2(pk2(acc[mt][nt][0], acc[mt][nt][1]), bb);
                ull v23 = add2(pk2(acc[mt][nt][2], acc[mt][nt][3]), bb);
                accp[mt][nt][0] = v01; accp[mt][nt][1] = v23;
                psA[2 * mt] = add2(psA[2 * mt], v01);
                pqA[2 * mt] = fma2(v01, v01, pqA[2 * mt]);
                psA[2 * mt + 1] = add2(psA[2 * mt + 1], v23);
                pqA[2 * mt + 1] = fma2(v23, v23, pqA[2 * mt + 1]);
            }
        float ps[4], pq[4];
#pragma unroll
        for (int rl = 0; rl < 4; rl++) {
            float2 pf = up2(psA[rl]); ps[rl] = pf.x + pf.y;
            float2 qf = up2(pqA[rl]); pq[rl] = qf.x + qf.y;
            ps[rl] += __shfl_xor_sync(0xffffffffu, ps[rl], 1);
            ps[rl] += __shfl_xor_sync(0xffffffffu, ps[rl], 2);
            pq[rl] += __shfl_xor_sync(0xffffffffu, pq[rl], 1);
            pq[rl] += __shfl_xor_sync(0xffffffffu, pq[rl], 2);
        }
        if (t == 0) {
#pragma unroll
            for (int rl = 0; rl < 4; rl++) {
                int row = R0 + 16 * (rl >> 1) + 8 * (rl & 1) + g;
                *(float2*)&partp[row * 8 + wc * 2] = make_float2(ps[rl], pq[rl]);
            }
        }
        __syncthreads();   // sync2: stats partials ready

        // ---- LN2 + SiLU in registers -> A-fragments ypk ----
        ull rs2[4], mr2[4];
#pragma unroll
        for (int rl = 0; rl < 4; rl++) {
            int row = R0 + 16 * (rl >> 1) + 8 * (rl & 1) + g;
            float4 pA = *(const float4*)&partp[row * 8];
            float4 pB = *(const float4*)&partp[row * 8 + 4];
            float s = pA.x + pA.z + pB.x + pB.z;
            float q = pA.y + pA.w + pB.y + pB.w;
            float mean = s * (1.f / 128.f);
            float var = q * (1.f / 128.f) - mean * mean;
            float rsv = rsqrtf(var + 1e-5f);
            float mrs = -mean * rsv;
            rs2[rl] = pk2(rsv, rsv);
            mr2[rl] = pk2(mrs, mrs);
        }
        uint32_t ypk[2][4][2];
#pragma unroll
        for (int mt = 0; mt < 2; mt++)
#pragma unroll
            for (int nt = 0; nt < 4; nt++) {
                int rl0 = 2 * mt, rl1 = 2 * mt + 1;
                ull gg = *(const ull*)&sg2[C0 + 8 * nt + 2 * t];
                ull ee = *(const ull*)&sbe2[C0 + 8 * nt + 2 * t];
                ull y01 = fma2(fma2(accp[mt][nt][0], rs2[rl0], mr2[rl0]), gg, ee);
                ull y23 = fma2(fma2(accp[mt][nt][1], rs2[rl1], mr2[rl1]), gg, ee);
                float2 s01 = up2(silu2p(y01));
                float2 s23 = up2(silu2p(y23));
                ypk[mt][nt][0] = packbf(s01.x, s01.y);   // row R0+16mt+g,   cols C0+8nt+2t..+1
                ypk[mt][nt][1] = packbf(s23.x, s23.y);   // row R0+16mt+8+g
            }

        // ---- GEMM2 from registers: partial X3 for this warp's K-slice ----
        float a3[2][2][4];
#pragma unroll
        for (int mt = 0; mt < 2; mt++)
#pragma unroll
            for (int nb = 0; nb < 2; nb++)
#pragma unroll
                for (int u = 0; u < 4; u++) a3[mt][nb][u] = 0.f;
#pragma unroll
        for (int kb2 = 0; kb2 < 2; kb2++) {
            uint32_t bb[4];
            ldsm4(bb, bAddr3 + kb2 * 32);
#pragma unroll
            for (int mt = 0; mt < 2; mt++) {
                uint32_t af[4] = { ypk[mt][2 * kb2][0], ypk[mt][2 * kb2][1],
                                   ypk[mt][2 * kb2 + 1][0], ypk[mt][2 * kb2 + 1][1] };
                mma16816(a3[mt][0], af, &bb[0]);
                mma16816(a3[mt][1], af, &bb[2]);
            }
        }
        // store bf16 partials: buffer wc, row pitch 10 words
        {
            uint32_t* p3 = P3w + wc * 640;
#pragma unroll
            for (int mt = 0; mt < 2; mt++)
#pragma unroll
                for (int nb = 0; nb < 2; nb++) {
                    int row = R0 + 16 * mt + g;
                    int w = 4 * nb + t;
                    p3[row * 10 + w] = packbf(a3[mt][nb][0], a3[mt][nb][1]);
                    p3[(row + 8) * 10 + w] = packbf(a3[mt][nb][2], a3[mt][nb][3]);
                }
        }
        __syncthreads();   // sync3: X3 partials ready

        // ---- scatter (warps 4-5): sum partials, transform, atomics ----
        if (warp == 4 || warp == 5) {
            int el = tid - 128;
            int e2 = ebase + el;
            const float* cdp = coord_diff + (size_t)e2 * 9;
            float cd[9];
#pragma unroll
            for (int c9 = 0; c9 < 9; c9++) cd[c9] = __ldg(cdp + c9);
            int r2 = __ldg(rowI + e2);
            float em = __ldg(edge_mask + e2);
            float ph[10];
#pragma unroll
            for (int w = 0; w < 5; w++) {
                ull sacc = add2(add2(bf2f2(P3w[el * 10 + w]), bf2f2(P3w[640 + el * 10 + w])),
                                add2(bf2f2(P3w[1280 + el * 10 + w]), bf2f2(P3w[1920 + el * 10 + w])));
                float2 f = up2(sacc);
                ph[2 * w] = f.x; ph[2 * w + 1] = f.y;
            }
            float* aggp = g_agg + (size_t)r2 * 9;
#pragma unroll
            for (int l = 0; l < 3; l++)
#pragma unroll
                for (int k = 0; k < 3; k++) {
                    float tr = cd[k] * ph[l] + cd[3 + k] * ph[3 + l] + cd[6 + k] * ph[6 + l];
                    atomicAdd(aggp + l * 3 + k, tr * em);
                }
        }
        // no trailing barrier: next Stage A writes XA (dead after sync1-consumers),
        // P3w/partp only rewritten after the next tile's sync2.
    }
}

__global__ void finalize_kernel(const float* __restrict__ coord,
                                const float* __restrict__ node_mask,
                                float* __restrict__ out) {
    int i = blockIdx.x * 256 + threadIdx.x;
    if (i < NNODES * 9) {
        out[i] = (coord[i] + g_agg[i] * 0.01f) * node_mask[i / 9];
    }
}

extern "C" void kernel_launch(void* const* d_in, const int* in_sizes, int n_in,
                              void* d_out, int out_size) {
    const float* h          = (const float*)d_in[0];
    const float* coord      = (const float*)d_in[1];
    const float* coord_diff = (const float*)d_in[2];
    const float* edge_attr  = (const float*)d_in[3];
    const float* edge_mask  = (const float*)d_in[4];
    const float* node_mask  = (const float*)d_in[5];
    const int*   rowI       = (const int*)d_in[6];
    const int*   colI       = (const int*)d_in[7];
    const float* W1  = (const float*)d_in[8];
    const float* b1  = (const float*)d_in[9];
    const float* g1  = (const float*)d_in[10];
    const float* be1 = (const float*)d_in[11];
    const float* W2  = (const float*)d_in[12];
    const float* b2  = (const float*)d_in[13];
    const float* g2  = (const float*)d_in[14];
    const float* be2 = (const float*)d_in[15];
    const float* W3  = (const float*)d_in[16];
    float* out = (float*)d_out;

    cudaFuncSetAttribute(hab_kernel, cudaFuncAttributeMaxDynamicSharedMemorySize, HAB_SMEM);
    cudaFuncSetAttribute(edge_kernel, cudaFuncAttributeMaxDynamicSharedMemorySize, EDGE_SMEM);

    prep_kernel<<<(NNODES * 9 + 255) / 256, 256>>>(W1);
    hab_kernel<<<dim3((NNODES + 63) / 64, 2), 256, HAB_SMEM>>>(h, b1);
    edge_kernel<<<444, 256, EDGE_SMEM>>>(W1, g1, be1, W2, b2, g2, be2, W3,
                                         rowI, colI, edge_attr, edge_mask, coord_diff);
    finalize_kernel<<<(NNODES * 9 + 255) / 256, 256>>>(coord, node_mask, out);
}

// round 9
// speedup vs baseline: 1.3982x; 1.0031x over previous
#include <cuda_runtime.h>
#include <cuda_bf16.h>
#include <cuda_fp16.h>
#include <stdint.h>

#define NNODES 50000
#define NEDGES 800000
#define MTILE 64
#define NTILES (NEDGES / MTILE)   // 12500

typedef unsigned long long ull;

// ---------------- scratch ----------------
__device__ __align__(128) __nv_bfloat16 g_hAB[(size_t)NNODES * 256];
__device__ __align__(128) __nv_bfloat16 g_W1T[2 * 128 * 128];
__device__ float g_sA[NNODES];
__device__ float g_sB[NNODES];
__device__ float g_agg[NNODES * 9];

// ---------------- helpers ----------------
static __device__ __forceinline__ uint32_t packbf(float a, float b) {
    __nv_bfloat162 h = __floats2bfloat162_rn(a, b);
    return *reinterpret_cast<uint32_t*>(&h);
}
// ---- packed f32x2 ----
static __device__ __forceinline__ ull pk2(float lo, float hi) {
    ull r; asm("mov.b64 %0, {%1, %2};" : "=l"(r) : "f"(lo), "f"(hi)); return r;
}
static __device__ __forceinline__ float2 up2(ull v) {
    float2 f; asm("mov.b64 {%0, %1}, %2;" : "=f"(f.x), "=f"(f.y) : "l"(v)); return f;
}
static __device__ __forceinline__ ull add2(ull a, ull b) {
    ull r; asm("add.rn.f32x2 %0, %1, %2;" : "=l"(r) : "l"(a), "l"(b)); return r;
}
static __device__ __forceinline__ ull mul2(ull a, ull b) {
    ull r; asm("mul.rn.f32x2 %0, %1, %2;" : "=l"(r) : "l"(a), "l"(b)); return r;
}
static __device__ __forceinline__ ull fma2(ull a, ull b, ull c) {
    ull r; asm("fma.rn.f32x2 %0, %1, %2, %3;" : "=l"(r) : "l"(a), "l"(b), "l"(c)); return r;
}
// bf16x2 word -> f32x2 (element order preserved)
static __device__ __forceinline__ ull bf2f2(uint32_t u) {
    uint32_t lo = u << 16;
    uint32_t hi = u & 0xFFFF0000u;
    ull r; asm("mov.b64 %0, {%1, %2};" : "=l"(r) : "r"(lo), "r"(hi)); return r;
}

static __device__ __forceinline__ void mma16816(float* c, const uint32_t* a, const uint32_t* b) {
    asm volatile(
        "mma.sync.aligned.m16n8k16.row.col.f32.bf16.bf16.f32 "
        "{%0,%1,%2,%3}, {%4,%5,%6,%7}, {%8,%9}, {%0,%1,%2,%3};\n"
        : "+f"(c[0]), "+f"(c[1]), "+f"(c[2]), "+f"(c[3])
        : "r"(a[0]), "r"(a[1]), "r"(a[2]), "r"(a[3]), "r"(b[0]), "r"(b[1]));
}
static __device__ __forceinline__ void ldsm4(uint32_t* r, uint32_t addr) {
    asm volatile("ldmatrix.sync.aligned.m8n8.x4.shared.b16 {%0,%1,%2,%3}, [%4];"
        : "=r"(r[0]), "=r"(r[1]), "=r"(r[2]), "=r"(r[3]) : "r"(addr));
}
// silu on a packed f32x2, computed natively in bf16x2, returns bf16x2 word:
// y_bf = cvt(y); h = y_bf * 0.5; t = tanh(h); silu = h + h*t
static __device__ __forceinline__ uint32_t silu2bf(ull y2) {
    float2 yf = up2(y2);
    uint32_t yb, hb, tb, rb;
    asm("cvt.rn.bf16x2.f32 %0, %1, %2;" : "=r"(yb) : "f"(yf.y), "f"(yf.x));
    asm("mul.rn.bf16x2 %0, %1, %2;" : "=r"(hb) : "r"(yb), "r"(0x3F003F00u));
    asm("tanh.approx.bf16x2 %0, %1;" : "=r"(tb) : "r"(hb));
    asm("fma.rn.bf16x2 %0, %1, %2, %3;" : "=r"(rb) : "r"(hb), "r"(tb), "r"(hb));
    return rb;
}
static __device__ __forceinline__ uint32_t s2u(const void* p) {
    return (uint32_t)__cvta_generic_to_shared(p);
}

// ---------------------------------------------------------------------------
// prep: W1 -> bf16 transposed halves; zero agg
// ---------------------------------------------------------------------------
__global__ void prep_kernel(const float* __restrict__ W1) {
    int i = blockIdx.x * 256 + threadIdx.x;
    if (i < 2 * 128 * 128) {
        int hb = i >> 14, n = (i >> 7) & 127, k = i & 127;
        g_W1T[i] = __float2bfloat16(W1[(size_t)(hb * 128 + k) * 128 + n]);
    }
    if (i < NNODES * 9) g_agg[i] = 0.f;
}

// ---------------------------------------------------------------------------
// hab: hA' = h @ W1[0:128] + b1 ; hB = h @ W1[128:256]; row sums to g_sA/g_sB
// ---------------------------------------------------------------------------
#define HAB_SMEM (17408 + 34816 + 1024)
__global__ void __launch_bounds__(256, 2)
hab_kernel(const float* __restrict__ h, const float* __restrict__ b1) {
    extern __shared__ unsigned char sm[];
    unsigned char* smA = sm;             // 64 x 272B
    unsigned char* smB = sm + 17408;     // 128 x 272B
    float* part = (float*)(sm + 52224);  // 64 x 4 floats

    const int tid = threadIdx.x;
    const int nt0 = blockIdx.x * 64;
    const int hb = blockIdx.y;

    for (int idx = tid; idx < 64 * 32; idx += 256) {
        int i = idx >> 5, kq = idx & 31;
        float4 v = make_float4(0.f, 0.f, 0.f, 0.f);
        if (nt0 + i < NNODES) v = *(const float4*)(h + (size_t)(nt0 + i) * 128 + kq * 4);
        *(uint2*)(smA + i * 272 + kq * 8) = make_uint2(packbf(v.x, v.y), packbf(v.z, v.w));
    }
    const uint4* w1src = (const uint4*)(g_W1T + (hb << 14));
    for (int idx = tid; idx < 128 * 16; idx += 256) {
        int n = idx >> 4, q = idx & 15;
        *(uint4*)(smB + n * 272 + q * 16) = w1src[idx];
    }
    __syncthreads();

    const int warp = tid >> 5, lane = tid & 31;
    const int lr = lane & 7, sel = lane >> 3, g = lane >> 2, t = lane & 3;
    const int R0 = (warp & 1) * 32, wc = warp >> 1, C0 = wc * 32;

    uint32_t aAddr[2], bAddr[2];
#pragma unroll
    for (int mt = 0; mt < 2; mt++)
        aAddr[mt] = s2u(smA + (R0 + 16 * mt + lr + (sel & 1) * 8) * 272 + (sel >> 1) * 16);
#pragma unroll
    for (int np = 0; np < 2; np++)
        bAddr[np] = s2u(smB + (C0 + 16 * np + lr + (sel >> 1) * 8) * 272 + (sel & 1) * 16);

    float acc[2][4][4];
#pragma unroll
    for (int mt = 0; mt < 2; mt++)
#pragma unroll
        for (int nt = 0; nt < 4; nt++)
#pragma unroll
            for (int u = 0; u < 4; u++) acc[mt][nt][u] = 0.f;

#pragma unroll
    for (int kb = 0; kb < 8; kb++) {
        uint32_t a[2][4], b[2][4];
        ldsm4(a[0], aAddr[0] + kb * 32);
        ldsm4(a[1], aAddr[1] + kb * 32);
        ldsm4(b[0], bAddr[0] + kb * 32);
        ldsm4(b[1], bAddr[1] + kb * 32);
#pragma unroll
        for (int mt = 0; mt < 2; mt++)
#pragma unroll
            for (int np = 0; np < 2; np++) {
                mma16816(acc[mt][2 * np], a[mt], &b[np][0]);
                mma16816(acc[mt][2 * np + 1], a[mt], &b[np][2]);
            }
    }

    float b1v[8];
#pragma unroll
    for (int nt = 0; nt < 4; nt++) {
        b1v[2 * nt] = (hb == 0) ? b1[C0 + 8 * nt + 2 * t] : 0.f;
        b1v[2 * nt + 1] = (hb == 0) ? b1[C0 + 8 * nt + 2 * t + 1] : 0.f;
    }

    float ps[4] = {0.f, 0.f, 0.f, 0.f};
    uint32_t* outw = (uint32_t*)g_hAB;
#pragma unroll
    for (int mt = 0; mt < 2; mt++)
#pragma unroll
        for (int nt = 0; nt < 4; nt++) {
            float v0 = acc[mt][nt][0] + b1v[2 * nt];
            float v1 = acc[mt][nt][1] + b1v[2 * nt + 1];
            float v2 = acc[mt][nt][2] + b1v[2 * nt];
            float v3 = acc[mt][nt][3] + b1v[2 * nt + 1];
            ps[2 * mt] += v0 + v1;
            ps[2 * mt + 1] += v2 + v3;
            int node0 = nt0 + R0 + 16 * mt + g;
            int cc = C0 + 8 * nt + 2 * t;
            if (node0 < NNODES)
                outw[((size_t)node0 * 256 + (hb << 7) + cc) >> 1] = packbf(v0, v1);
            if (node0 + 8 < NNODES)
                outw[((size_t)(node0 + 8) * 256 + (hb << 7) + cc) >> 1] = packbf(v2, v3);
        }
#pragma unroll
    for (int rl = 0; rl < 4; rl++) {
        ps[rl] += __shfl_xor_sync(0xffffffffu, ps[rl], 1);
        ps[rl] += __shfl_xor_sync(0xffffffffu, ps[rl], 2);
    }
    if (t == 0) {
#pragma unroll
        for (int rl = 0; rl < 4; rl++) {
            int row = R0 + 16 * (rl >> 1) + 8 * (rl & 1) + g;
            part[row * 4 + wc] = ps[rl];
        }
    }
    __syncthreads();
    if (tid < 64) {
        int node = nt0 + tid;
        if (node < NNODES) {
            float s = part[tid * 4] + part[tid * 4 + 1] + part[tid * 4 + 2] + part[tid * 4 + 3];
            if (hb == 0) g_sA[node] = s; else g_sB[node] = s;
        }
    }
}

// ---------------------------------------------------------------------------
// edge kernel (occ 3): 3-barrier pipeline, register GEMM2, bf16x2 silu
// ---------------------------------------------------------------------------
#define OFF_XA   0                 // 64 x 272B  (X1 only)
#define OFF_W2   17408             // 128 x 272B
#define OFF_W3   52224             // 16 x 272B
#define OFF_P3   56576             // 4 x 64 x 40B  X3 bf16 partials per warp-col
#define OFF_PART 66816             // 64 x 8 f32 (LN2 stats partials)
#define OFF_PAR  68864             // params
#define EDGE_SMEM 72512

__global__ void __launch_bounds__(256, 3)
edge_kernel(const float* __restrict__ W1, const float* __restrict__ g1,
            const float* __restrict__ be1,
            const float* __restrict__ W2, const float* __restrict__ b2,
            const float* __restrict__ g2, const float* __restrict__ be2,
            const float* __restrict__ W3,
            const int* __restrict__ rowI, const int* __restrict__ colI,
            const float* __restrict__ edge_attr, const float* __restrict__ edge_mask,
            const float* __restrict__ coord_diff) {
    extern __shared__ unsigned char sm[];
    unsigned char* smXA = sm + OFF_XA;
    uint32_t* XAw = (uint32_t*)smXA;
    __nv_bfloat16* W2h = (__nv_bfloat16*)(sm + OFF_W2);
    __nv_bfloat16* W3h = (__nv_bfloat16*)(sm + OFF_W3);
    uint32_t* P3w = (uint32_t*)(sm + OFF_P3);          // [wc][row][10 words]
    float* partp = (float*)(sm + OFF_PART);
    float* par = (float*)(sm + OFF_PAR);
    float* sw1c = par;           float* sg1 = par + 128;  float* sbe1 = par + 256;
    float* sb2 = par + 384;      float* sg2 = par + 512;  float* sbe2 = par + 640;
    float* sSw = par + 768;

    const int tid = threadIdx.x;
    if (tid < 128) {
        sw1c[tid] = W1[256 * 128 + tid];
        sg1[tid] = g1[tid]; sbe1[tid] = be1[tid];
        sb2[tid] = b2[tid]; sg2[tid] = g2[tid]; sbe2[tid] = be2[tid];
    }
    for (int idx = tid; idx < 128 * 128; idx += 256) {
        int k = idx >> 7, n = idx & 127;
        W2h[n * 136 + k] = __float2bfloat16(W2[idx]);
    }
    for (int idx = tid; idx < 16 * 128; idx += 256) {
        int n = idx >> 7, k = idx & 127;
        W3h[n * 136 + k] = __float2bfloat16(n < 9 ? W3[k * 9 + n] : 0.f);
    }
    __syncthreads();

    const int warp = tid >> 5, lane = tid & 31;
    const int lr = lane & 7, sel = lane >> 3, g = lane >> 2, t = lane & 3;
    const int R0 = (warp & 1) * 32, wc = warp >> 1, C0 = wc * 32;
    const int j0 = lane * 4;

    if (warp == 0) {
        float s = sw1c[lane] + sw1c[lane + 32] + sw1c[lane + 64] + sw1c[lane + 96];
#pragma unroll
        for (int o = 16; o > 0; o >>= 1) s += __shfl_xor_sync(0xffffffffu, s, o);
        if (lane == 0) sSw[0] = s;
    }
    __syncthreads();

    // packed per-lane LN1 parameters
    const ull w01  = *(const ull*)&sw1c[j0],  w23  = *(const ull*)&sw1c[j0 + 2];
    const ull g01  = *(const ull*)&sg1[j0],   g23  = *(const ull*)&sg1[j0 + 2];
    const ull be01 = *(const ull*)&sbe1[j0],  be23 = *(const ull*)&sbe1[j0 + 2];
    const float Sw = sSw[0];

    // ldmatrix base addresses
    uint32_t aAddr[2], bAddr[2];
#pragma unroll
    for (int mt = 0; mt < 2; mt++)
        aAddr[mt] = s2u(smXA + (R0 + 16 * mt + lr + (sel & 1) * 8) * 272 + (sel >> 1) * 16);
#pragma unroll
    for (int np = 0; np < 2; np++)
        bAddr[np] = s2u(sm + OFF_W2 + (C0 + 16 * np + lr + (sel >> 1) * 8) * 272 + (sel & 1) * 16);
    // W3 B-operand base: this warp's K-slice starts at col C0 -> byte 2*C0
    const uint32_t bAddr3 = s2u(sm + OFF_W3 + (lr + (sel >> 1) * 8) * 272 + (sel & 1) * 16) + wc * 64;

    for (int tile = blockIdx.x; tile < NTILES; tile += gridDim.x) {
        const int ebase = tile * MTILE;
        const int e0 = ebase + warp * 8;

        // ---- Stage A: gather + LN1 + SiLU -> XA (bf16), depth-3 pipeline ----
        int rs8[8], cs8[8]; float eas[8];
#pragma unroll
        for (int it = 0; it < 8; it++) {
            rs8[it] = __ldg(rowI + e0 + it);
            cs8[it] = __ldg(colI + e0 + it);
            eas[it] = __ldg(edge_attr + e0 + it);
        }
        uint2 pwa[3], pwb[3]; float psa[3], psb[3];
#pragma unroll
        for (int p = 0; p < 3; p++) {
            pwa[p] = *(const uint2*)(g_hAB + (size_t)rs8[p] * 256 + j0);
            pwb[p] = *(const uint2*)(g_hAB + (size_t)cs8[p] * 256 + 128 + j0);
            psa[p] = __ldg(g_sA + rs8[p]);
            psb[p] = __ldg(g_sB + cs8[p]);
        }
#pragma unroll
        for (int it = 0; it < 8; it++) {
            const int s = it % 3;
            uint2 wa = pwa[s], wb = pwb[s];
            float sums = psa[s] + psb[s];
            float ea = eas[it];
            if (it + 3 < 8) {
                pwa[s] = *(const uint2*)(g_hAB + (size_t)rs8[it + 3] * 256 + j0);
                pwb[s] = *(const uint2*)(g_hAB + (size_t)cs8[it + 3] * 256 + 128 + j0);
                psa[s] = __ldg(g_sA + rs8[it + 3]);
                psb[s] = __ldg(g_sB + cs8[it + 3]);
            }
            ull a01 = bf2f2(wa.x), a23 = bf2f2(wa.y);
            ull f01 = bf2f2(wb.x), f23 = bf2f2(wb.y);
            ull ea2 = pk2(ea, ea);
            ull x01 = fma2(ea2, w01, add2(a01, f01));
            ull x23 = fma2(ea2, w23, add2(a23, f23));
            ull q2 = fma2(x01, x01, mul2(x23, x23));
            float2 qf = up2(q2);
            float q = qf.x + qf.y;
#pragma unroll
            for (int o = 16; o > 0; o >>= 1) q += __shfl_xor_sync(0xffffffffu, q, o);
            float mean = (sums + ea * Sw) * (1.f / 128.f);
            float var = q * (1.f / 128.f) - mean * mean;
            float rsv = rsqrtf(var + 1e-5f);
            float mrs = -mean * rsv;
            ull rsv2 = pk2(rsv, rsv), mrs2 = pk2(mrs, mrs);
            ull y01 = fma2(fma2(x01, rsv2, mrs2), g01, be01);
            ull y23 = fma2(fma2(x23, rsv2, mrs2), g23, be23);
            *(uint2*)&XAw[(warp * 8 + it) * 68 + lane * 2] =
                make_uint2(silu2bf(y01), silu2bf(y23));
        }
        __syncthreads();   // sync1: X1 ready

        // ---- GEMM1: acc = X1 @ W2 ----
        float acc[2][4][4];
#pragma unroll
        for (int mt = 0; mt < 2; mt++)
#pragma unroll
            for (int nt = 0; nt < 4; nt++)
#pragma unroll
                for (int u = 0; u < 4; u++) acc[mt][nt][u] = 0.f;
#pragma unroll
        for (int kb = 0; kb < 8; kb++) {
            uint32_t a[2][4], b[2][4];
            ldsm4(a[0], aAddr[0] + kb * 32);
            ldsm4(a[1], aAddr[1] + kb * 32);
            ldsm4(b[0], bAddr[0] + kb * 32);
            ldsm4(b[1], bAddr[1] + kb * 32);
#pragma unroll
            for (int mt = 0; mt < 2; mt++)
#pragma unroll
                for (int np = 0; np < 2; np++) {
                    mma16816(acc[mt][2 * np], a[mt], &b[np][0]);
                    mma16816(acc[mt][2 * np + 1], a[mt], &b[np][2]);
                }
        }
        // bias + per-row partial sums (for LN2), packed f32x2
        ull accp[2][4][2];
        ull psA[4], pqA[4];
#pragma unroll
        for (int rl = 0; rl < 4; rl++) { psA[rl] = 0ull; pqA[rl] = 0ull; }
#pragma unroll
        for (int mt = 0; mt < 2; mt++)
#pragma unroll
            for (int nt = 0; nt < 4; nt++) {
                ull bb = *(const ull*)&sb2[C0 + 8 * nt + 2 * t];
                ull v01 = add2(pk2(acc[mt][nt][0], acc[mt][nt][1]), bb);
                ull v23 = add2(pk2(acc[mt][nt][2], acc[mt][nt][3]), bb);
                accp[mt][nt][0] = v01; accp[mt][nt][1] = v23;
                psA[2 * mt] = add2(psA[2 * mt], v01);
                pqA[2 * mt] = fma2(v01, v01, pqA[2 * mt]);
                psA[2 * mt + 1] = add2(psA[2 * mt + 1], v23);
                pqA[2 * mt + 1] = fma2(v23, v23, pqA[2 * mt + 1]);
            }
        float ps[4], pq[4];
#pragma unroll
        for (int rl = 0; rl < 4; rl++) {
            float2 pf = up2(psA[rl]); ps[rl] = pf.x + pf.y;
            float2 qf = up2(pqA[rl]); pq[rl] = qf.x + qf.y;
            ps[rl] += __shfl_xor_sync(0xffffffffu, ps[rl], 1);
            ps[rl] += __shfl_xor_sync(0xffffffffu, ps[rl], 2);
            pq[rl] += __shfl_xor_sync(0xffffffffu, pq[rl], 1);
            pq[rl] += __shfl_xor_sync(0xffffffffu, pq[rl], 2);
        }
        if (t == 0) {
#pragma unroll
            for (int rl = 0; rl < 4; rl++) {
                int row = R0 + 16 * (rl >> 1) + 8 * (rl & 1) + g;
                *(float2*)&partp[row * 8 + wc * 2] = make_float2(ps[rl], pq[rl]);
            }
        }
        __syncthreads();   // sync2: stats partials ready

        // ---- LN2 + SiLU in registers -> A-fragments ypk (bf16x2) ----
        ull rs2[4], mr2[4];
#pragma unroll
        for (int rl = 0; rl < 4; rl++) {
            int row = R0 + 16 * (rl >> 1) + 8 * (rl & 1) + g;
            float4 pA = *(const float4*)&partp[row * 8];
            float4 pB = *(const float4*)&partp[row * 8 + 4];
            float s = pA.x + pA.z + pB.x + pB.z;
            float q = pA.y + pA.w + pB.y + pB.w;
            float mean = s * (1.f / 128.f);
            float var = q * (1.f / 128.f) - mean * mean;
            float rsv = rsqrtf(var + 1e-5f);
            float mrs = -mean * rsv;
            rs2[rl] = pk2(rsv, rsv);
            mr2[rl] = pk2(mrs, mrs);
        }
        uint32_t ypk[2][4][2];
#pragma unroll
        for (int mt = 0; mt < 2; mt++)
#pragma unroll
            for (int nt = 0; nt < 4; nt++) {
                int rl0 = 2 * mt, rl1 = 2 * mt + 1;
                ull gg = *(const ull*)&sg2[C0 + 8 * nt + 2 * t];
                ull ee = *(const ull*)&sbe2[C0 + 8 * nt + 2 * t];
                ull y01 = fma2(fma2(accp[mt][nt][0], rs2[rl0], mr2[rl0]), gg, ee);
                ull y23 = fma2(fma2(accp[mt][nt][1], rs2[rl1], mr2[rl1]), gg, ee);
                ypk[mt][nt][0] = silu2bf(y01);   // row R0+16mt+g,   cols C0+8nt+2t..+1
                ypk[mt][nt][1] = silu2bf(y23);   // row R0+16mt+8+g
            }

        // ---- GEMM2 from registers: partial X3 for this warp's K-slice ----
        float a3[2][2][4];
#pragma unroll
        for (int mt = 0; mt < 2; mt++)
#pragma unroll
            for (int nb = 0; nb < 2; nb++)
#pragma unroll
                for (int u = 0; u < 4; u++) a3[mt][nb][u] = 0.f;
#pragma unroll
        for (int kb2 = 0; kb2 < 2; kb2++) {
            uint32_t bb[4];
            ldsm4(bb, bAddr3 + kb2 * 32);
#pragma unroll
            for (int mt = 0; mt < 2; mt++) {
                uint32_t af[4] = { ypk[mt][2 * kb2][0], ypk[mt][2 * kb2][1],
                                   ypk[mt][2 * kb2 + 1][0], ypk[mt][2 * kb2 + 1][1] };
                mma16816(a3[mt][0], af, &bb[0]);
                mma16816(a3[mt][1], af, &bb[2]);
            }
        }
        // store bf16 partials: buffer wc, row pitch 10 words
        {
            uint32_t* p3 = P3w + wc * 640;
#pragma unroll
            for (int mt = 0; mt < 2; mt++)
#pragma unroll
                for (int nb = 0; nb < 2; nb++) {
                    int row = R0 + 16 * mt + g;
                    int w = 4 * nb + t;
                    p3[row * 10 + w] = packbf(a3[mt][nb][0], a3[mt][nb][1]);
                    p3[(row + 8) * 10 + w] = packbf(a3[mt][nb][2], a3[mt][nb][3]);
                }
        }

        // ---- preload scatter operands so their latency overlaps sync3 ----
        float cd[9]; int r2 = 0; float em = 0.f;
        if (warp == 4 || warp == 5) {
            int el = tid - 128;
            int e2 = ebase + el;
            const float* cdp = coord_diff + (size_t)e2 * 9;
#pragma unroll
            for (int c9 = 0; c9 < 9; c9++) cd[c9] = __ldg(cdp + c9);
            r2 = __ldg(rowI + e2);
            em = __ldg(edge_mask + e2);
        }
        __syncthreads();   // sync3: X3 partials ready

        // ---- scatter (warps 4-5): sum partials, transform, atomics ----
        if (warp == 4 || warp == 5) {
            int el = tid - 128;
            float ph[10];
#pragma unroll
            for (int w = 0; w < 5; w++) {
                ull sacc = add2(add2(bf2f2(P3w[el * 10 + w]), bf2f2(P3w[640 + el * 10 + w])),
                                add2(bf2f2(P3w[1280 + el * 10 + w]), bf2f2(P3w[1920 + el * 10 + w])));
                float2 f = up2(sacc);
                ph[2 * w] = f.x; ph[2 * w + 1] = f.y;
            }
            float* aggp = g_agg + (size_t)r2 * 9;
#pragma unroll
            for (int l = 0; l < 3; l++)
#pragma unroll
                for (int k = 0; k < 3; k++) {
                    float tr = cd[k] * ph[l] + cd[3 + k] * ph[3 + l] + cd[6 + k] * ph[6 + l];
                    atomicAdd(aggp + l * 3 + k, tr * em);
                }
        }
        // no trailing barrier: next Stage A writes XA (dead after sync1-consumers),
        // P3w/partp only rewritten after the next tile's sync2.
    }
}

__global__ void finalize_kernel(const float* __restrict__ coord,
                                const float* __restrict__ node_mask,
                                float* __restrict__ out) {
    int i = blockIdx.x * 256 + threadIdx.x;
    if (i < NNODES * 9) {
        out[i] = (coord[i] + g_agg[i] * 0.01f) * node_mask[i / 9];
    }
}

extern "C" void kernel_launch(void* const* d_in, const int* in_sizes, int n_in,
                              void* d_out, int out_size) {
    const float* h          = (const float*)d_in[0];
    const float* coord      = (const float*)d_in[1];
    const float* coord_diff = (const float*)d_in[2];
    const float* edge_attr  = (const float*)d_in[3];
    const float* edge_mask  = (const float*)d_in[4];
    const float* node_mask  = (const float*)d_in[5];
    const int*   rowI       = (const int*)d_in[6];
    const int*   colI       = (const int*)d_in[7];
    const float* W1  = (const float*)d_in[8];
    const float* b1  = (const float*)d_in[9];
    const float* g1  = (const float*)d_in[10];
    const float* be1 = (const float*)d_in[11];
    const float* W2  = (const float*)d_in[12];
    const float* b2  = (const float*)d_in[13];
    const float* g2  = (const float*)d_in[14];
    const float* be2 = (const float*)d_in[15];
    const float* W3  = (const float*)d_in[16];
    float* out = (float*)d_out;

    cudaFuncSetAttribute(hab_kernel, cudaFuncAttributeMaxDynamicSharedMemorySize, HAB_SMEM);
    cudaFuncSetAttribute(edge_kernel, cudaFuncAttributeMaxDynamicSharedMemorySize, EDGE_SMEM);

    prep_kernel<<<(NNODES * 9 + 255) / 256, 256>>>(W1);
    hab_kernel<<<dim3((NNODES + 63) / 64, 2), 256, HAB_SMEM>>>(h, b1);
    edge_kernel<<<444, 256, EDGE_SMEM>>>(W1, g1, be1, W2, b2, g2, be2, W3,
                                         rowI, colI, edge_attr, edge_mask, coord_diff);
    finalize_kernel<<<(NNODES * 9 + 255) / 256, 256>>>(coord, node_mask, out);
}